// round 6
// baseline (speedup 1.0000x reference)
#include <cuda_runtime.h>
#include <cuda_bf16.h>
#include <cstdint>
#include <math.h>

// ---------------- problem constants ------------------------------------------
#define BATCH   2
#define LQ      15000
#define ROWS    (BATCH * LQ)      // 30000
#define CDIM    256
#define HEADS   8
#define HDIM    32
#define NPTS    4
#define HL      100
#define WL      150
#define LS      (HL * WL)

// ---------------- scratch ----------------------------------------------------
__device__ __align__(16) float          g_buf0[ROWS * CDIM];
__device__ __align__(16) float          g_buf1[ROWS * CDIM];
__device__ __align__(16) float          g_buf2[ROWS * CDIM];
__device__ __align__(16) float          g_oa  [ROWS * 128];
__device__ __align__(16) __nv_bfloat16  g_shi [ROWS * CDIM];
__device__ __align__(16) __nv_bfloat16  g_slo [ROWS * CDIM];
__device__ __align__(16) __nv_bfloat16  g_wt_hi[4 * 65536];    // [w][n][k]: dsa,val,comb,ff
__device__ __align__(16) __nv_bfloat16  g_wt_lo[4 * 65536];
__device__ __align__(16) __nv_bfloat16  g_woa_hi[128 * 256];   // padded to 128 n
__device__ __align__(16) __nv_bfloat16  g_woa_lo[128 * 256];
__device__ __align__(16) float          g_boa[128];
__device__ __align__(16) float          g_wcomb[65536];        // W_out @ W_csa (fp32)
__device__ __align__(16) float          g_bcomb[256];

// ---------------- ptx helpers ------------------------------------------------
__device__ __forceinline__ uint32_t smem_u32(const void* p) {
    uint32_t a;
    asm("{ .reg .u64 t; cvta.to.shared.u64 t, %1; cvt.u32.u64 %0, t; }" : "=r"(a) : "l"(p));
    return a;
}
__device__ __forceinline__ void cpa16(uint32_t dst, const void* src, uint32_t sz) {
    asm volatile("cp.async.cg.shared.global [%0], [%1], 16, %2;"
                 :: "r"(dst), "l"(src), "r"(sz));
}
__device__ __forceinline__ void ldm_x4(uint32_t* r, uint32_t addr) {
    asm volatile("ldmatrix.sync.aligned.m8n8.x4.shared.b16 {%0,%1,%2,%3}, [%4];"
                 : "=r"(r[0]), "=r"(r[1]), "=r"(r[2]), "=r"(r[3]) : "r"(addr));
}
__device__ __forceinline__ void mma_bf16(float* d, const uint32_t* a, const uint32_t* b) {
    asm volatile("mma.sync.aligned.m16n8k16.row.col.f32.bf16.bf16.f32 "
        "{%0,%1,%2,%3}, {%4,%5,%6,%7}, {%8,%9}, {%0,%1,%2,%3};"
        : "+f"(d[0]), "+f"(d[1]), "+f"(d[2]), "+f"(d[3])
        : "r"(a[0]), "r"(a[1]), "r"(a[2]), "r"(a[3]), "r"(b[0]), "r"(b[1]));
}

// ---------------- split helper ----------------------------------------------
__device__ __forceinline__ void split2(float x, __nv_bfloat16& h, __nv_bfloat16& l) {
    h = __float2bfloat16(x);
    l = __float2bfloat16(x - __bfloat162float(h));
}

// ---------------- W_comb = W_out @ W_csa, b_comb = b_out @ W_csa + b_csa ------
__global__ void comb_kernel(const float* __restrict__ Wo, const float* __restrict__ Wc,
                            const float* __restrict__ bo, const float* __restrict__ bc)
{
    const int n = threadIdx.x;        // 0..255
    const int k = blockIdx.x;         // 0..255
    float s = 0.f;
#pragma unroll 8
    for (int j = 0; j < 256; j++) s = fmaf(Wo[k * 256 + j], Wc[j * 256 + n], s);
    g_wcomb[k * 256 + n] = s;
    if (k == 0) {
        float sb = 0.f;
#pragma unroll 8
        for (int j = 0; j < 256; j++) sb = fmaf(bo[j], Wc[j * 256 + n], sb);
        g_bcomb[n] = sb + bc[n];
    }
}

// ---------------- weight prep: transpose + bf16 split ------------------------
#define PREP_TOT (4 * 65536 + 128 * 256 + 128)
__global__ void prep_kernel(const float* __restrict__ Wd, const float* __restrict__ Wv,
                            const float* __restrict__ Wf, const float* __restrict__ Woff,
                            const float* __restrict__ Watt, const float* __restrict__ boff,
                            const float* __restrict__ batt)
{
    int idx = blockIdx.x * 256 + threadIdx.x;
    if (idx < 4 * 65536) {
        int w = idx >> 16, e = idx & 65535, n = e >> 8, k = e & 255;
        float v;
        if (w == 0)      v = Wd[k * 256 + n];
        else if (w == 1) v = Wv[k * 256 + n];
        else if (w == 2) v = g_wcomb[k * 256 + n];
        else             v = Wf[k * 256 + n];
        __nv_bfloat16 h, l; split2(v, h, l);
        g_wt_hi[w * 65536 + n * 256 + k] = h;
        g_wt_lo[w * 65536 + n * 256 + k] = l;
    } else if (idx < 4 * 65536 + 128 * 256) {
        int e = idx - 4 * 65536, n = e >> 8, k = e & 255;
        float v = 0.f;
        if (n < 64)       v = Woff[k * 64 + n];
        else if (n < 96)  v = Watt[k * 32 + (n - 64)];
        __nv_bfloat16 h, l; split2(v, h, l);
        g_woa_hi[n * 256 + k] = h;
        g_woa_lo[n * 256 + k] = l;
    } else if (idx < PREP_TOT) {
        int j = idx - (4 * 65536 + 128 * 256);
        g_boa[j] = (j < 64) ? boff[j] : (j < 96 ? batt[j - 64] : 0.f);
    }
}

// ---------------- elementwise split kernels -----------------------------------
__global__ void split_src_kernel(const float* __restrict__ x,
                                 __nv_bfloat16* __restrict__ hi, __nv_bfloat16* __restrict__ lo)
{
    int base = (blockIdx.x * 256 + threadIdx.x) * 4;
    if (base >= ROWS * CDIM) return;
    float4 v = *(const float4*)(x + base);
    union { __nv_bfloat16 b[4]; uint2 u; } ph, pl;
    split2(v.x, ph.b[0], pl.b[0]); split2(v.y, ph.b[1], pl.b[1]);
    split2(v.z, ph.b[2], pl.b[2]); split2(v.w, ph.b[3], pl.b[3]);
    *(uint2*)(hi + base) = ph.u;
    *(uint2*)(lo + base) = pl.u;
}

__global__ void add_split_kernel(const float* __restrict__ a, const float* __restrict__ b,
                                 __nv_bfloat16* __restrict__ hi, __nv_bfloat16* __restrict__ lo)
{
    int base = (blockIdx.x * 256 + threadIdx.x) * 4;
    if (base >= ROWS * CDIM) return;
    float4 va = *(const float4*)(a + base);
    float4 vb = *(const float4*)(b + base);
    union { __nv_bfloat16 bb[4]; uint2 u; } ph, pl;
    split2(va.x + vb.x, ph.bb[0], pl.bb[0]); split2(va.y + vb.y, ph.bb[1], pl.bb[1]);
    split2(va.z + vb.z, ph.bb[2], pl.bb[2]); split2(va.w + vb.w, ph.bb[3], pl.bb[3]);
    *(uint2*)(hi + base) = ph.u;
    *(uint2*)(lo + base) = pl.u;
}

// ---------------- warp-per-row layernorm kernels ------------------------------
__device__ __forceinline__ float warp_sum(float v)
{
#pragma unroll
    for (int o = 16; o > 0; o >>= 1) v += __shfl_xor_sync(0xffffffffu, v, o);
    return v;
}

// y = LN(x)*g+b -> split only
__global__ void ln_split_warp(const float* __restrict__ x, const float* __restrict__ g,
                              const float* __restrict__ b,
                              __nv_bfloat16* __restrict__ hi, __nv_bfloat16* __restrict__ lo)
{
    const int w = threadIdx.x >> 5, lane = threadIdx.x & 31;
    const int row = blockIdx.x * 8 + w;
    const float4* xr = (const float4*)(x + (size_t)row * 256) + lane * 2;
    float4 v0 = xr[0], v1 = xr[1];
    float vv[8] = {v0.x, v0.y, v0.z, v0.w, v1.x, v1.y, v1.z, v1.w};
    float s = 0.f;
#pragma unroll
    for (int i = 0; i < 8; i++) s += vv[i];
    float mean = warp_sum(s) * (1.f / 256);
    float va = 0.f;
#pragma unroll
    for (int i = 0; i < 8; i++) { vv[i] -= mean; va += vv[i] * vv[i]; }
    float rs = rsqrtf(warp_sum(va) * (1.f / 256) + 1e-5f);
    float4 g0 = ((const float4*)g)[lane * 2], g1 = ((const float4*)g)[lane * 2 + 1];
    float4 b0 = ((const float4*)b)[lane * 2], b1 = ((const float4*)b)[lane * 2 + 1];
    float gg[8] = {g0.x, g0.y, g0.z, g0.w, g1.x, g1.y, g1.z, g1.w};
    float bb[8] = {b0.x, b0.y, b0.z, b0.w, b1.x, b1.y, b1.z, b1.w};
    union { __nv_bfloat16 h[8]; uint4 u; } ph, pl;
#pragma unroll
    for (int i = 0; i < 8; i++) {
        float y = vv[i] * rs * gg[i] + bb[i];
        split2(y, ph.h[i], pl.h[i]);
    }
    *(uint4*)(hi + (size_t)row * 256 + lane * 8) = ph.u;
    *(uint4*)(lo + (size_t)row * 256 + lane * 8) = pl.u;
}

// t = LN(a+c)*g+b -> y (f32) + split
__global__ void addln_split_warp(const float* __restrict__ a, const float* __restrict__ c,
                                 const float* __restrict__ g, const float* __restrict__ b,
                                 float* __restrict__ y,
                                 __nv_bfloat16* __restrict__ hi, __nv_bfloat16* __restrict__ lo)
{
    const int w = threadIdx.x >> 5, lane = threadIdx.x & 31;
    const int row = blockIdx.x * 8 + w;
    const float4* ar = (const float4*)(a + (size_t)row * 256) + lane * 2;
    const float4* cr = (const float4*)(c + (size_t)row * 256) + lane * 2;
    float4 a0 = ar[0], a1 = ar[1], c0 = cr[0], c1 = cr[1];
    float vv[8] = {a0.x + c0.x, a0.y + c0.y, a0.z + c0.z, a0.w + c0.w,
                   a1.x + c1.x, a1.y + c1.y, a1.z + c1.z, a1.w + c1.w};
    float s = 0.f;
#pragma unroll
    for (int i = 0; i < 8; i++) s += vv[i];
    float mean = warp_sum(s) * (1.f / 256);
    float va = 0.f;
#pragma unroll
    for (int i = 0; i < 8; i++) { vv[i] -= mean; va += vv[i] * vv[i]; }
    float rs = rsqrtf(warp_sum(va) * (1.f / 256) + 1e-5f);
    float4 g0 = ((const float4*)g)[lane * 2], g1 = ((const float4*)g)[lane * 2 + 1];
    float4 b0 = ((const float4*)b)[lane * 2], b1 = ((const float4*)b)[lane * 2 + 1];
    float gg[8] = {g0.x, g0.y, g0.z, g0.w, g1.x, g1.y, g1.z, g1.w};
    float bb[8] = {b0.x, b0.y, b0.z, b0.w, b1.x, b1.y, b1.z, b1.w};
    union { __nv_bfloat16 h[8]; uint4 u; } ph, pl;
    float out8[8];
#pragma unroll
    for (int i = 0; i < 8; i++) {
        float o = vv[i] * rs * gg[i] + bb[i];
        out8[i] = o;
        split2(o, ph.h[i], pl.h[i]);
    }
    float4* yr = (float4*)(y + (size_t)row * 256) + lane * 2;
    yr[0] = make_float4(out8[0], out8[1], out8[2], out8[3]);
    yr[1] = make_float4(out8[4], out8[5], out8[6], out8[7]);
    *(uint4*)(hi + (size_t)row * 256 + lane * 8) = ph.u;
    *(uint4*)(lo + (size_t)row * 256 + lane * 8) = pl.u;
}

// y = LN(a+c)*g+b (f32 only)
__global__ void addln_warp(const float* __restrict__ a, const float* __restrict__ c,
                           const float* __restrict__ g, const float* __restrict__ b,
                           float* __restrict__ y)
{
    const int w = threadIdx.x >> 5, lane = threadIdx.x & 31;
    const int row = blockIdx.x * 8 + w;
    const float4* ar = (const float4*)(a + (size_t)row * 256) + lane * 2;
    const float4* cr = (const float4*)(c + (size_t)row * 256) + lane * 2;
    float4 a0 = ar[0], a1 = ar[1], c0 = cr[0], c1 = cr[1];
    float vv[8] = {a0.x + c0.x, a0.y + c0.y, a0.z + c0.z, a0.w + c0.w,
                   a1.x + c1.x, a1.y + c1.y, a1.z + c1.z, a1.w + c1.w};
    float s = 0.f;
#pragma unroll
    for (int i = 0; i < 8; i++) s += vv[i];
    float mean = warp_sum(s) * (1.f / 256);
    float va = 0.f;
#pragma unroll
    for (int i = 0; i < 8; i++) { vv[i] -= mean; va += vv[i] * vv[i]; }
    float rs = rsqrtf(warp_sum(va) * (1.f / 256) + 1e-5f);
    float4 g0 = ((const float4*)g)[lane * 2], g1 = ((const float4*)g)[lane * 2 + 1];
    float4 b0 = ((const float4*)b)[lane * 2], b1 = ((const float4*)b)[lane * 2 + 1];
    float gg[8] = {g0.x, g0.y, g0.z, g0.w, g1.x, g1.y, g1.z, g1.w};
    float bb[8] = {b0.x, b0.y, b0.z, b0.w, b1.x, b1.y, b1.z, b1.w};
    float out8[8];
#pragma unroll
    for (int i = 0; i < 8; i++) out8[i] = vv[i] * rs * gg[i] + bb[i];
    float4* yr = (float4*)(y + (size_t)row * 256) + lane * 2;
    yr[0] = make_float4(out8[0], out8[1], out8[2], out8[3]);
    yr[1] = make_float4(out8[4], out8[5], out8[6], out8[7]);
}

// ---------------- deformable sampling ----------------------------------------
__device__ __forceinline__ float fetch_v(const float* __restrict__ vbase, int x, int y)
{
    if (x < 0 || x >= WL || y < 0 || y >= HL) return 0.f;
    return vbase[(size_t)(y * WL + x) * CDIM];
}

__global__ void msda_kernel(const float* __restrict__ value, const float* __restrict__ oa,
                            const float* __restrict__ ref,
                            __nv_bfloat16* __restrict__ ohi, __nv_bfloat16* __restrict__ olo)
{
    const int warp = blockIdx.x * (blockDim.x >> 5) + (threadIdx.x >> 5);
    const int lane = threadIdx.x & 31;
    if (warp >= ROWS * HEADS) return;
    const int hd = warp & 7;
    const int bq = warp >> 3;
    const int b  = bq / LQ;

    const float* oarow = oa + (size_t)bq * 128;
    float a0 = oarow[64 + hd * 4 + 0];
    float a1 = oarow[64 + hd * 4 + 1];
    float a2 = oarow[64 + hd * 4 + 2];
    float a3 = oarow[64 + hd * 4 + 3];
    float m  = fmaxf(fmaxf(a0, a1), fmaxf(a2, a3));
    float e0 = expf(a0 - m), e1 = expf(a1 - m), e2 = expf(a2 - m), e3 = expf(a3 - m);
    float inv = 1.f / (e0 + e1 + e2 + e3);
    float w[4] = {e0 * inv, e1 * inv, e2 * inv, e3 * inv};

    const float rx = ref[(size_t)bq * 2 + 0];
    const float ry = ref[(size_t)bq * 2 + 1];
    const float* vbase = value + (size_t)b * LS * CDIM + hd * HDIM + lane;

    float acc = 0.f;
#pragma unroll
    for (int p = 0; p < NPTS; p++) {
        float ox = oarow[hd * 8 + p * 2 + 0];
        float oy = oarow[hd * 8 + p * 2 + 1];
        float X = (rx + ox / (float)WL) * (float)WL - 0.5f;
        float Y = (ry + oy / (float)HL) * (float)HL - 0.5f;
        float x0f = floorf(X), y0f = floorf(Y);
        float lx = X - x0f, ly = Y - y0f;
        int x0 = (int)x0f, y0 = (int)y0f;
        float s00 = fetch_v(vbase, x0,     y0);
        float s10 = fetch_v(vbase, x0 + 1, y0);
        float s01 = fetch_v(vbase, x0,     y0 + 1);
        float s11 = fetch_v(vbase, x0 + 1, y0 + 1);
        float sv  = s00 * (1.f - lx) * (1.f - ly) + s10 * lx * (1.f - ly)
                  + s01 * (1.f - lx) * ly         + s11 * lx * ly;
        acc = fmaf(w[p], sv, acc);
    }
    split2(acc, ohi[(size_t)bq * CDIM + hd * HDIM + lane],
                olo[(size_t)bq * CDIM + hd * HDIM + lane]);
}

// ---------------- mma.sync GEMM (512 threads, 16 warps) -----------------------
// C[ROWS, N] = (Ahi+Alo) @ (Bhi+Blo)^T + bias   (B stored [n][k], K contiguous)
// 3-term: Ah*Bh + Al*Bh + Ah*Bl.  BM=128 BN=128 BK=32, 3-stage cp.async.
// Warp grid 4(M) x 4(N); warp tile 32x32.
#define GSTAGE 40960
#define GSMEM  (3 * GSTAGE)

template<bool GELU, bool WF32, bool WSPLIT>
__global__ void __launch_bounds__(512, 1) mgemm_kernel(
    const __nv_bfloat16* __restrict__ Ahi, const __nv_bfloat16* __restrict__ Alo,
    const __nv_bfloat16* __restrict__ Bhi, const __nv_bfloat16* __restrict__ Blo,
    const float* __restrict__ bias,
    float* __restrict__ outF, int ldo,
    __nv_bfloat16* __restrict__ outH, __nv_bfloat16* __restrict__ outL)
{
    extern __shared__ __align__(128) char smem[];
    const int tid = threadIdx.x, lane = tid & 31, wid = tid >> 5;
    const int row0 = blockIdx.x * 128, n0 = blockIdx.y * 128;
    const int wm = wid >> 2, wn = wid & 3;           // 4 x 4 warp grid
    const uint32_t sbase = smem_u32(smem);

    float acc[2][4][4];
#pragma unroll
    for (int i = 0; i < 2; i++)
#pragma unroll
        for (int j = 0; j < 4; j++)
#pragma unroll
            for (int q = 0; q < 4; q++) acc[i][j][q] = 0.f;

    auto load_stage = [&](int c, int s) {
        const int kk = c * 32;
        const uint32_t st = sbase + s * GSTAGE;
        int r = tid >> 2, cc = tid & 3;              // 512 threads = 512 granules/tile
        uint32_t so = (uint32_t)(r * 80 + cc * 16);
        int gr = row0 + r;
        uint32_t sz = (gr < ROWS) ? 16u : 0u;
        cpa16(st + so,         Ahi + (size_t)gr * 256 + kk + cc * 8, sz);
        cpa16(st + 10240 + so, Alo + (size_t)gr * 256 + kk + cc * 8, sz);
        cpa16(st + 20480 + so, Bhi + (size_t)(n0 + r) * 256 + kk + cc * 8, 16u);
        cpa16(st + 30720 + so, Blo + (size_t)(n0 + r) * 256 + kk + cc * 8, 16u);
        asm volatile("cp.async.commit_group;" ::: "memory");
    };

    load_stage(0, 0);
    load_stage(1, 1);

#pragma unroll 1
    for (int c = 0; c < 8; c++) {
        if (c < 7) asm volatile("cp.async.wait_group 1;" ::: "memory");
        else       asm volatile("cp.async.wait_group 0;" ::: "memory");
        __syncthreads();

        const uint32_t st = sbase + (c % 3) * GSTAGE;
#pragma unroll
        for (int k16 = 0; k16 < 2; k16++) {
            uint32_t ah[2][4], al[2][4], bh[4][2], bl[4][2];
            {
                int ar = wm * 32 + (lane & 15);
                int ac = k16 * 16 + ((lane >> 4) << 3);
#pragma unroll
                for (int mi = 0; mi < 2; mi++) {
                    uint32_t ad = st + (uint32_t)((ar + mi * 16) * 80 + ac * 2);
                    ldm_x4(ah[mi], ad);
                    ldm_x4(al[mi], ad + 10240);
                }
            }
            {
                int br = wn * 32 + ((lane >> 4) << 3) + (lane & 7);
                int bc = k16 * 16 + ((lane >> 3) & 1) * 8;
#pragma unroll
                for (int p = 0; p < 2; p++) {
                    uint32_t bd = st + 20480 + (uint32_t)((br + p * 16) * 80 + bc * 2);
                    uint32_t t4[4];
                    ldm_x4(t4, bd);
                    bh[2 * p][0] = t4[0]; bh[2 * p][1] = t4[1];
                    bh[2 * p + 1][0] = t4[2]; bh[2 * p + 1][1] = t4[3];
                    ldm_x4(t4, bd + 10240);
                    bl[2 * p][0] = t4[0]; bl[2 * p][1] = t4[1];
                    bl[2 * p + 1][0] = t4[2]; bl[2 * p + 1][1] = t4[3];
                }
            }
#pragma unroll
            for (int mi = 0; mi < 2; mi++)
#pragma unroll
                for (int nj = 0; nj < 4; nj++) {
                    mma_bf16(acc[mi][nj], ah[mi], bh[nj]);
                    mma_bf16(acc[mi][nj], al[mi], bh[nj]);
                    mma_bf16(acc[mi][nj], ah[mi], bl[nj]);
                }
        }
        if (c <= 5) load_stage(c + 2, (c + 2) % 3);
    }

#pragma unroll
    for (int mi = 0; mi < 2; mi++) {
        int rl = row0 + wm * 32 + mi * 16 + (lane >> 2);
        int rh = rl + 8;
#pragma unroll
        for (int nj = 0; nj < 4; nj++) {
            int col = n0 + wn * 32 + nj * 8 + (lane & 3) * 2;
            float b0 = __ldg(&bias[col]), b1 = __ldg(&bias[col + 1]);
            float v0 = acc[mi][nj][0] + b0, v1 = acc[mi][nj][1] + b1;
            float v2 = acc[mi][nj][2] + b0, v3 = acc[mi][nj][3] + b1;
            if (GELU) {
                v0 = 0.5f * v0 * (1.f + erff(v0 * 0.70710678118654752f));
                v1 = 0.5f * v1 * (1.f + erff(v1 * 0.70710678118654752f));
                v2 = 0.5f * v2 * (1.f + erff(v2 * 0.70710678118654752f));
                v3 = 0.5f * v3 * (1.f + erff(v3 * 0.70710678118654752f));
            }
            if (WF32) {
                if (rl < ROWS) *(float2*)(outF + (size_t)rl * ldo + col) = make_float2(v0, v1);
                if (rh < ROWS) *(float2*)(outF + (size_t)rh * ldo + col) = make_float2(v2, v3);
            }
            if (WSPLIT) {
                union { __nv_bfloat16 b[2]; uint32_t u; } h0, l0, h1, l1;
                split2(v0, h0.b[0], l0.b[0]); split2(v1, h0.b[1], l0.b[1]);
                split2(v2, h1.b[0], l1.b[0]); split2(v3, h1.b[1], l1.b[1]);
                if (rl < ROWS) {
                    *(uint32_t*)(outH + (size_t)rl * 256 + col) = h0.u;
                    *(uint32_t*)(outL + (size_t)rl * 256 + col) = l0.u;
                }
                if (rh < ROWS) {
                    *(uint32_t*)(outH + (size_t)rh * 256 + col) = h1.u;
                    *(uint32_t*)(outL + (size_t)rh * 256 + col) = l1.u;
                }
            }
        }
    }
}

// ---------------- launch -------------------------------------------------------
extern "C" void kernel_launch(void* const* d_in, const int* in_sizes, int n_in,
                              void* d_out, int out_size)
{
    const float* tgt       = (const float*)d_in[0];
    const float* query_pos = (const float*)d_in[1];
    const float* refpts    = (const float*)d_in[4];
    const float* src       = (const float*)d_in[6];
    const float* W_dsa = (const float*)d_in[10]; const float* b_dsa = (const float*)d_in[11];
    const float* g_nds = (const float*)d_in[12]; const float* b_nds = (const float*)d_in[13];
    const float* W_off = (const float*)d_in[14]; const float* b_off = (const float*)d_in[15];
    const float* W_att = (const float*)d_in[16]; const float* b_att = (const float*)d_in[17];
    const float* W_val = (const float*)d_in[18]; const float* b_val = (const float*)d_in[19];
    const float* W_out = (const float*)d_in[20]; const float* b_out = (const float*)d_in[21];
    const float* W_csa = (const float*)d_in[22]; const float* b_csa = (const float*)d_in[23];
    const float* g_n1  = (const float*)d_in[24]; const float* b_n1  = (const float*)d_in[25];
    const float* W_ff  = (const float*)d_in[26]; const float* b_ff  = (const float*)d_in[27];
    const float* g_n3  = (const float*)d_in[28]; const float* b_n3  = (const float*)d_in[29];
    float* out = (float*)d_out;

    float *buf0, *buf1, *buf2, *oa, *boa, *bcomb;
    __nv_bfloat16 *shi, *slo, *wth, *wtl, *woah, *woal;
    cudaGetSymbolAddress((void**)&buf0,  g_buf0);
    cudaGetSymbolAddress((void**)&buf1,  g_buf1);
    cudaGetSymbolAddress((void**)&buf2,  g_buf2);
    cudaGetSymbolAddress((void**)&oa,    g_oa);
    cudaGetSymbolAddress((void**)&boa,   g_boa);
    cudaGetSymbolAddress((void**)&bcomb, g_bcomb);
    cudaGetSymbolAddress((void**)&shi,   g_shi);
    cudaGetSymbolAddress((void**)&slo,   g_slo);
    cudaGetSymbolAddress((void**)&wth,   g_wt_hi);
    cudaGetSymbolAddress((void**)&wtl,   g_wt_lo);
    cudaGetSymbolAddress((void**)&woah,  g_woa_hi);
    cudaGetSymbolAddress((void**)&woal,  g_woa_lo);

    cudaFuncSetAttribute((const void*)mgemm_kernel<false, true,  false>,
                         cudaFuncAttributeMaxDynamicSharedMemorySize, GSMEM);
    cudaFuncSetAttribute((const void*)mgemm_kernel<true,  true,  false>,
                         cudaFuncAttributeMaxDynamicSharedMemorySize, GSMEM);

    const int MT  = (ROWS + 127) / 128;       // 235 row tiles
    const dim3 gFull(MT, 2);                  // N = 256
    const dim3 gOA  (MT, 1);                  // N = 128 (96 padded)
    const int EW4 = (ROWS * CDIM / 4 + 255) / 256;
    const int LNB = ROWS / 8;                 // 3750 warp-LN blocks

    // 0) combined weight + prep
    comb_kernel<<<256, 256>>>(W_out, W_csa, b_out, b_csa);
    prep_kernel<<<(PREP_TOT + 255) / 256, 256>>>(W_dsa, W_val, W_ff,
                                                 W_off, W_att, b_off, b_att);
    // 1) split src
    split_src_kernel<<<EW4, 256>>>(src, shi, slo);
    // 2) dsa GEMM -> buf0 (f32)
    mgemm_kernel<false, true, false><<<gFull, 512, GSMEM>>>(
        shi, slo, wth + 0 * 65536, wtl + 0 * 65536, b_dsa, buf0, 256, nullptr, nullptr);
    // 3) LN(nds) -> split
    ln_split_warp<<<LNB, 256>>>(buf0, g_nds, b_nds, shi, slo);
    // 4) value GEMM -> buf0 (f32)
    mgemm_kernel<false, true, false><<<gFull, 512, GSMEM>>>(
        shi, slo, wth + 1 * 65536, wtl + 1 * 65536, b_val, buf0, 256, nullptr, nullptr);
    // 5) q = tgt + query_pos -> split
    add_split_kernel<<<EW4, 256>>>(tgt, query_pos, shi, slo);
    // 6) offsets+attention GEMM (N=128 padded) -> oa
    mgemm_kernel<false, true, false><<<gOA, 512, GSMEM>>>(
        shi, slo, woah, woal, boa, oa, 128, nullptr, nullptr);
    // 7) deformable sampling -> split (shi/slo)
    msda_kernel<<<(ROWS * HEADS + 7) / 8, 256>>>(buf0, oa, refpts, shi, slo);
    // 8) combined out+csa GEMM -> buf1 (f32)
    mgemm_kernel<false, true, false><<<gFull, 512, GSMEM>>>(
        shi, slo, wth + 2 * 65536, wtl + 2 * 65536, bcomb, buf1, 256, nullptr, nullptr);
    // 9) t = LN(tgt + tgt2) -> buf2 (f32) + split
    addln_split_warp<<<LNB, 256>>>(tgt, buf1, g_n1, b_n1, buf2, shi, slo);
    // 10) ff = gelu(t @ W_ff + b_ff) -> buf0 (f32)
    mgemm_kernel<true, true, false><<<gFull, 512, GSMEM>>>(
        shi, slo, wth + 3 * 65536, wtl + 3 * 65536, b_ff, buf0, 256, nullptr, nullptr);
    // 11) out = LN(t + ff)
    addln_warp<<<LNB, 256>>>(buf2, buf0, g_n3, b_n3, out);
}

// round 7
// speedup vs baseline: 1.0205x; 1.0205x over previous
#include <cuda_runtime.h>
#include <cuda_bf16.h>
#include <cstdint>
#include <math.h>

// ---------------- problem constants ------------------------------------------
#define BATCH   2
#define LQ      15000
#define ROWS    (BATCH * LQ)      // 30000
#define CDIM    256
#define HEADS   8
#define HDIM    32
#define NPTS    4
#define HL      100
#define WL      150
#define LS      (HL * WL)

// ---------------- scratch ----------------------------------------------------
__device__ __align__(16) float          g_buf0[ROWS * CDIM];
__device__ __align__(16) float          g_buf1[ROWS * CDIM];
__device__ __align__(16) float          g_buf2[ROWS * CDIM];
__device__ __align__(16) float          g_oa  [ROWS * 128];
__device__ __align__(16) __nv_bfloat16  g_shi [ROWS * CDIM];
__device__ __align__(16) __nv_bfloat16  g_slo [ROWS * CDIM];
__device__ __align__(16) __nv_bfloat16  g_wt_hi[4 * 65536];    // [w][n][k]: dsa,val,comb,ff
__device__ __align__(16) __nv_bfloat16  g_wt_lo[4 * 65536];
__device__ __align__(16) __nv_bfloat16  g_woa_hi[128 * 256];   // padded to 128 n
__device__ __align__(16) __nv_bfloat16  g_woa_lo[128 * 256];
__device__ __align__(16) float          g_boa[128];
__device__ __align__(16) float          g_wcomb[65536];        // W_out @ W_csa (fp32)
__device__ __align__(16) float          g_bcomb[256];

// ---------------- ptx helpers ------------------------------------------------
__device__ __forceinline__ uint32_t smem_u32(const void* p) {
    uint32_t a;
    asm("{ .reg .u64 t; cvta.to.shared.u64 t, %1; cvt.u32.u64 %0, t; }" : "=r"(a) : "l"(p));
    return a;
}
__device__ __forceinline__ void cpa16(uint32_t dst, const void* src, uint32_t sz) {
    asm volatile("cp.async.cg.shared.global [%0], [%1], 16, %2;"
                 :: "r"(dst), "l"(src), "r"(sz));
}
__device__ __forceinline__ void ldm_x4(uint32_t* r, uint32_t addr) {
    asm volatile("ldmatrix.sync.aligned.m8n8.x4.shared.b16 {%0,%1,%2,%3}, [%4];"
                 : "=r"(r[0]), "=r"(r[1]), "=r"(r[2]), "=r"(r[3]) : "r"(addr));
}
__device__ __forceinline__ void mma_bf16(float* d, const uint32_t* a, const uint32_t* b) {
    asm volatile("mma.sync.aligned.m16n8k16.row.col.f32.bf16.bf16.f32 "
        "{%0,%1,%2,%3}, {%4,%5,%6,%7}, {%8,%9}, {%0,%1,%2,%3};"
        : "+f"(d[0]), "+f"(d[1]), "+f"(d[2]), "+f"(d[3])
        : "r"(a[0]), "r"(a[1]), "r"(a[2]), "r"(a[3]), "r"(b[0]), "r"(b[1]));
}

// ---------------- split helper ----------------------------------------------
__device__ __forceinline__ void split2(float x, __nv_bfloat16& h, __nv_bfloat16& l) {
    h = __float2bfloat16(x);
    l = __float2bfloat16(x - __bfloat162float(h));
}

// ---------------- W_comb = W_out @ W_csa, b_comb = b_out @ W_csa + b_csa ------
__global__ void comb_kernel(const float* __restrict__ Wo, const float* __restrict__ Wc,
                            const float* __restrict__ bo, const float* __restrict__ bc)
{
    const int n = threadIdx.x;        // 0..255
    const int k = blockIdx.x;         // 0..255
    float s = 0.f;
#pragma unroll 8
    for (int j = 0; j < 256; j++) s = fmaf(Wo[k * 256 + j], Wc[j * 256 + n], s);
    g_wcomb[k * 256 + n] = s;
    if (k == 0) {
        float sb = 0.f;
#pragma unroll 8
        for (int j = 0; j < 256; j++) sb = fmaf(bo[j], Wc[j * 256 + n], sb);
        g_bcomb[n] = sb + bc[n];
    }
}

// ---------------- weight prep: transpose + bf16 split ------------------------
#define PREP_TOT (4 * 65536 + 128 * 256 + 128)
__global__ void prep_kernel(const float* __restrict__ Wd, const float* __restrict__ Wv,
                            const float* __restrict__ Wf, const float* __restrict__ Woff,
                            const float* __restrict__ Watt, const float* __restrict__ boff,
                            const float* __restrict__ batt)
{
    int idx = blockIdx.x * 256 + threadIdx.x;
    if (idx < 4 * 65536) {
        int w = idx >> 16, e = idx & 65535, n = e >> 8, k = e & 255;
        float v;
        if (w == 0)      v = Wd[k * 256 + n];
        else if (w == 1) v = Wv[k * 256 + n];
        else if (w == 2) v = g_wcomb[k * 256 + n];
        else             v = Wf[k * 256 + n];
        __nv_bfloat16 h, l; split2(v, h, l);
        g_wt_hi[w * 65536 + n * 256 + k] = h;
        g_wt_lo[w * 65536 + n * 256 + k] = l;
    } else if (idx < 4 * 65536 + 128 * 256) {
        int e = idx - 4 * 65536, n = e >> 8, k = e & 255;
        float v = 0.f;
        if (n < 64)       v = Woff[k * 64 + n];
        else if (n < 96)  v = Watt[k * 32 + (n - 64)];
        __nv_bfloat16 h, l; split2(v, h, l);
        g_woa_hi[n * 256 + k] = h;
        g_woa_lo[n * 256 + k] = l;
    } else if (idx < PREP_TOT) {
        int j = idx - (4 * 65536 + 128 * 256);
        g_boa[j] = (j < 64) ? boff[j] : (j < 96 ? batt[j - 64] : 0.f);
    }
}

// ---------------- elementwise split kernels -----------------------------------
__global__ void split_src_kernel(const float* __restrict__ x,
                                 __nv_bfloat16* __restrict__ hi, __nv_bfloat16* __restrict__ lo)
{
    int base = (blockIdx.x * 256 + threadIdx.x) * 4;
    if (base >= ROWS * CDIM) return;
    float4 v = *(const float4*)(x + base);
    union { __nv_bfloat16 b[4]; uint2 u; } ph, pl;
    split2(v.x, ph.b[0], pl.b[0]); split2(v.y, ph.b[1], pl.b[1]);
    split2(v.z, ph.b[2], pl.b[2]); split2(v.w, ph.b[3], pl.b[3]);
    *(uint2*)(hi + base) = ph.u;
    *(uint2*)(lo + base) = pl.u;
}

__global__ void add_split_kernel(const float* __restrict__ a, const float* __restrict__ b,
                                 __nv_bfloat16* __restrict__ hi, __nv_bfloat16* __restrict__ lo)
{
    int base = (blockIdx.x * 256 + threadIdx.x) * 4;
    if (base >= ROWS * CDIM) return;
    float4 va = *(const float4*)(a + base);
    float4 vb = *(const float4*)(b + base);
    union { __nv_bfloat16 bb[4]; uint2 u; } ph, pl;
    split2(va.x + vb.x, ph.bb[0], pl.bb[0]); split2(va.y + vb.y, ph.bb[1], pl.bb[1]);
    split2(va.z + vb.z, ph.bb[2], pl.bb[2]); split2(va.w + vb.w, ph.bb[3], pl.bb[3]);
    *(uint2*)(hi + base) = ph.u;
    *(uint2*)(lo + base) = pl.u;
}

// ---------------- warp-per-row layernorm kernels ------------------------------
__device__ __forceinline__ float warp_sum(float v)
{
#pragma unroll
    for (int o = 16; o > 0; o >>= 1) v += __shfl_xor_sync(0xffffffffu, v, o);
    return v;
}

__global__ void ln_split_warp(const float* __restrict__ x, const float* __restrict__ g,
                              const float* __restrict__ b,
                              __nv_bfloat16* __restrict__ hi, __nv_bfloat16* __restrict__ lo)
{
    const int w = threadIdx.x >> 5, lane = threadIdx.x & 31;
    const int row = blockIdx.x * 8 + w;
    const float4* xr = (const float4*)(x + (size_t)row * 256) + lane * 2;
    float4 v0 = xr[0], v1 = xr[1];
    float vv[8] = {v0.x, v0.y, v0.z, v0.w, v1.x, v1.y, v1.z, v1.w};
    float s = 0.f;
#pragma unroll
    for (int i = 0; i < 8; i++) s += vv[i];
    float mean = warp_sum(s) * (1.f / 256);
    float va = 0.f;
#pragma unroll
    for (int i = 0; i < 8; i++) { vv[i] -= mean; va += vv[i] * vv[i]; }
    float rs = rsqrtf(warp_sum(va) * (1.f / 256) + 1e-5f);
    float4 g0 = ((const float4*)g)[lane * 2], g1 = ((const float4*)g)[lane * 2 + 1];
    float4 b0 = ((const float4*)b)[lane * 2], b1 = ((const float4*)b)[lane * 2 + 1];
    float gg[8] = {g0.x, g0.y, g0.z, g0.w, g1.x, g1.y, g1.z, g1.w};
    float bb[8] = {b0.x, b0.y, b0.z, b0.w, b1.x, b1.y, b1.z, b1.w};
    union { __nv_bfloat16 h[8]; uint4 u; } ph, pl;
#pragma unroll
    for (int i = 0; i < 8; i++) {
        float y = vv[i] * rs * gg[i] + bb[i];
        split2(y, ph.h[i], pl.h[i]);
    }
    *(uint4*)(hi + (size_t)row * 256 + lane * 8) = ph.u;
    *(uint4*)(lo + (size_t)row * 256 + lane * 8) = pl.u;
}

__global__ void addln_split_warp(const float* __restrict__ a, const float* __restrict__ c,
                                 const float* __restrict__ g, const float* __restrict__ b,
                                 float* __restrict__ y,
                                 __nv_bfloat16* __restrict__ hi, __nv_bfloat16* __restrict__ lo)
{
    const int w = threadIdx.x >> 5, lane = threadIdx.x & 31;
    const int row = blockIdx.x * 8 + w;
    const float4* ar = (const float4*)(a + (size_t)row * 256) + lane * 2;
    const float4* cr = (const float4*)(c + (size_t)row * 256) + lane * 2;
    float4 a0 = ar[0], a1 = ar[1], c0 = cr[0], c1 = cr[1];
    float vv[8] = {a0.x + c0.x, a0.y + c0.y, a0.z + c0.z, a0.w + c0.w,
                   a1.x + c1.x, a1.y + c1.y, a1.z + c1.z, a1.w + c1.w};
    float s = 0.f;
#pragma unroll
    for (int i = 0; i < 8; i++) s += vv[i];
    float mean = warp_sum(s) * (1.f / 256);
    float va = 0.f;
#pragma unroll
    for (int i = 0; i < 8; i++) { vv[i] -= mean; va += vv[i] * vv[i]; }
    float rs = rsqrtf(warp_sum(va) * (1.f / 256) + 1e-5f);
    float4 g0 = ((const float4*)g)[lane * 2], g1 = ((const float4*)g)[lane * 2 + 1];
    float4 b0 = ((const float4*)b)[lane * 2], b1 = ((const float4*)b)[lane * 2 + 1];
    float gg[8] = {g0.x, g0.y, g0.z, g0.w, g1.x, g1.y, g1.z, g1.w};
    float bb[8] = {b0.x, b0.y, b0.z, b0.w, b1.x, b1.y, b1.z, b1.w};
    union { __nv_bfloat16 h[8]; uint4 u; } ph, pl;
    float out8[8];
#pragma unroll
    for (int i = 0; i < 8; i++) {
        float o = vv[i] * rs * gg[i] + bb[i];
        out8[i] = o;
        split2(o, ph.h[i], pl.h[i]);
    }
    float4* yr = (float4*)(y + (size_t)row * 256) + lane * 2;
    yr[0] = make_float4(out8[0], out8[1], out8[2], out8[3]);
    yr[1] = make_float4(out8[4], out8[5], out8[6], out8[7]);
    *(uint4*)(hi + (size_t)row * 256 + lane * 8) = ph.u;
    *(uint4*)(lo + (size_t)row * 256 + lane * 8) = pl.u;
}

__global__ void addln_warp(const float* __restrict__ a, const float* __restrict__ c,
                           const float* __restrict__ g, const float* __restrict__ b,
                           float* __restrict__ y)
{
    const int w = threadIdx.x >> 5, lane = threadIdx.x & 31;
    const int row = blockIdx.x * 8 + w;
    const float4* ar = (const float4*)(a + (size_t)row * 256) + lane * 2;
    const float4* cr = (const float4*)(c + (size_t)row * 256) + lane * 2;
    float4 a0 = ar[0], a1 = ar[1], c0 = cr[0], c1 = cr[1];
    float vv[8] = {a0.x + c0.x, a0.y + c0.y, a0.z + c0.z, a0.w + c0.w,
                   a1.x + c1.x, a1.y + c1.y, a1.z + c1.z, a1.w + c1.w};
    float s = 0.f;
#pragma unroll
    for (int i = 0; i < 8; i++) s += vv[i];
    float mean = warp_sum(s) * (1.f / 256);
    float va = 0.f;
#pragma unroll
    for (int i = 0; i < 8; i++) { vv[i] -= mean; va += vv[i] * vv[i]; }
    float rs = rsqrtf(warp_sum(va) * (1.f / 256) + 1e-5f);
    float4 g0 = ((const float4*)g)[lane * 2], g1 = ((const float4*)g)[lane * 2 + 1];
    float4 b0 = ((const float4*)b)[lane * 2], b1 = ((const float4*)b)[lane * 2 + 1];
    float gg[8] = {g0.x, g0.y, g0.z, g0.w, g1.x, g1.y, g1.z, g1.w};
    float bb[8] = {b0.x, b0.y, b0.z, b0.w, b1.x, b1.y, b1.z, b1.w};
    float out8[8];
#pragma unroll
    for (int i = 0; i < 8; i++) out8[i] = vv[i] * rs * gg[i] + bb[i];
    float4* yr = (float4*)(y + (size_t)row * 256) + lane * 2;
    yr[0] = make_float4(out8[0], out8[1], out8[2], out8[3]);
    yr[1] = make_float4(out8[4], out8[5], out8[6], out8[7]);
}

// ---------------- deformable sampling ----------------------------------------
__device__ __forceinline__ float fetch_v(const float* __restrict__ vbase, int x, int y)
{
    if (x < 0 || x >= WL || y < 0 || y >= HL) return 0.f;
    return vbase[(size_t)(y * WL + x) * CDIM];
}

__global__ void msda_kernel(const float* __restrict__ value, const float* __restrict__ oa,
                            const float* __restrict__ ref,
                            __nv_bfloat16* __restrict__ ohi, __nv_bfloat16* __restrict__ olo)
{
    const int warp = blockIdx.x * (blockDim.x >> 5) + (threadIdx.x >> 5);
    const int lane = threadIdx.x & 31;
    if (warp >= ROWS * HEADS) return;
    const int hd = warp & 7;
    const int bq = warp >> 3;
    const int b  = bq / LQ;

    const float* oarow = oa + (size_t)bq * 128;
    float a0 = oarow[64 + hd * 4 + 0];
    float a1 = oarow[64 + hd * 4 + 1];
    float a2 = oarow[64 + hd * 4 + 2];
    float a3 = oarow[64 + hd * 4 + 3];
    float m  = fmaxf(fmaxf(a0, a1), fmaxf(a2, a3));
    float e0 = expf(a0 - m), e1 = expf(a1 - m), e2 = expf(a2 - m), e3 = expf(a3 - m);
    float inv = 1.f / (e0 + e1 + e2 + e3);
    float w[4] = {e0 * inv, e1 * inv, e2 * inv, e3 * inv};

    const float rx = ref[(size_t)bq * 2 + 0];
    const float ry = ref[(size_t)bq * 2 + 1];
    const float* vbase = value + (size_t)b * LS * CDIM + hd * HDIM + lane;

    float acc = 0.f;
#pragma unroll
    for (int p = 0; p < NPTS; p++) {
        float ox = oarow[hd * 8 + p * 2 + 0];
        float oy = oarow[hd * 8 + p * 2 + 1];
        float X = (rx + ox / (float)WL) * (float)WL - 0.5f;
        float Y = (ry + oy / (float)HL) * (float)HL - 0.5f;
        float x0f = floorf(X), y0f = floorf(Y);
        float lx = X - x0f, ly = Y - y0f;
        int x0 = (int)x0f, y0 = (int)y0f;
        float s00 = fetch_v(vbase, x0,     y0);
        float s10 = fetch_v(vbase, x0 + 1, y0);
        float s01 = fetch_v(vbase, x0,     y0 + 1);
        float s11 = fetch_v(vbase, x0 + 1, y0 + 1);
        float sv  = s00 * (1.f - lx) * (1.f - ly) + s10 * lx * (1.f - ly)
                  + s01 * (1.f - lx) * ly         + s11 * lx * ly;
        acc = fmaf(w[p], sv, acc);
    }
    split2(acc, ohi[(size_t)bq * CDIM + hd * HDIM + lane],
                olo[(size_t)bq * CDIM + hd * HDIM + lane]);
}

// ---------------- mma.sync GEMM (128 threads, 4 warps, 64x64 warp tiles) ------
// C[ROWS, N] = (Ahi+Alo) @ (Bhi+Blo)^T + bias   (B stored [n][k], K contiguous)
// 3-term: Ah*Bh + Al*Bh + Ah*Bl.  BM=128 BN=128 BK=32, 2-stage cp.async,
// 2 CTAs/SM.  Warp grid 2(M) x 2(N); warp tile 64x64.
// LDSM traffic per iter: 2x16 + 2x16 = 64 KB (half of the 4x4-grid layout).
#define GSTAGE 40960
#define GSMEM  (2 * GSTAGE)

template<bool GELU, bool WF32, bool WSPLIT>
__global__ void __launch_bounds__(128, 2) mgemm_kernel(
    const __nv_bfloat16* __restrict__ Ahi, const __nv_bfloat16* __restrict__ Alo,
    const __nv_bfloat16* __restrict__ Bhi, const __nv_bfloat16* __restrict__ Blo,
    const float* __restrict__ bias,
    float* __restrict__ outF, int ldo,
    __nv_bfloat16* __restrict__ outH, __nv_bfloat16* __restrict__ outL)
{
    extern __shared__ __align__(128) char smem[];
    const int tid = threadIdx.x, lane = tid & 31, wid = tid >> 5;
    const int row0 = blockIdx.x * 128, n0 = blockIdx.y * 128;
    const int wm = wid >> 1, wn = wid & 1;           // 2 x 2 warp grid
    const uint32_t sbase = smem_u32(smem);

    float acc[4][8][4];
#pragma unroll
    for (int i = 0; i < 4; i++)
#pragma unroll
        for (int j = 0; j < 8; j++)
#pragma unroll
            for (int q = 0; q < 4; q++) acc[i][j][q] = 0.f;

    auto load_stage = [&](int c, int s) {
        const int kk = c * 32;
        const uint32_t st = sbase + s * GSTAGE;
#pragma unroll
        for (int i = 0; i < 4; i++) {
            int g = i * 128 + tid;                   // 0..511 granules per matrix
            int r = g >> 2, cc = g & 3;
            uint32_t so = (uint32_t)(r * 80 + cc * 16);
            int gr = row0 + r;
            uint32_t sz = (gr < ROWS) ? 16u : 0u;
            cpa16(st + so,         Ahi + (size_t)gr * 256 + kk + cc * 8, sz);
            cpa16(st + 10240 + so, Alo + (size_t)gr * 256 + kk + cc * 8, sz);
            cpa16(st + 20480 + so, Bhi + (size_t)(n0 + r) * 256 + kk + cc * 8, 16u);
            cpa16(st + 30720 + so, Blo + (size_t)(n0 + r) * 256 + kk + cc * 8, 16u);
        }
        asm volatile("cp.async.commit_group;" ::: "memory");
    };

    load_stage(0, 0);
    load_stage(1, 1);

#pragma unroll 1
    for (int c = 0; c < 8; c++) {
        if (c < 7) asm volatile("cp.async.wait_group 1;" ::: "memory");
        else       asm volatile("cp.async.wait_group 0;" ::: "memory");
        __syncthreads();

        const uint32_t st = sbase + (c & 1) * GSTAGE;
#pragma unroll
        for (int k16 = 0; k16 < 2; k16++) {
            uint32_t bh[8][2], bl[8][2];
            {
                int br = wn * 64 + ((lane >> 4) << 3) + (lane & 7);
                int bc = k16 * 16 + ((lane >> 3) & 1) * 8;
#pragma unroll
                for (int p = 0; p < 4; p++) {
                    uint32_t bd = st + 20480 + (uint32_t)((br + p * 16) * 80 + bc * 2);
                    uint32_t t4[4];
                    ldm_x4(t4, bd);
                    bh[2 * p][0] = t4[0]; bh[2 * p][1] = t4[1];
                    bh[2 * p + 1][0] = t4[2]; bh[2 * p + 1][1] = t4[3];
                    ldm_x4(t4, bd + 10240);
                    bl[2 * p][0] = t4[0]; bl[2 * p][1] = t4[1];
                    bl[2 * p + 1][0] = t4[2]; bl[2 * p + 1][1] = t4[3];
                }
            }
            int ar = wm * 64 + (lane & 15);
            int ac = k16 * 16 + ((lane >> 4) << 3);
#pragma unroll
            for (int mi = 0; mi < 4; mi++) {
                uint32_t ah[4], al[4];
                uint32_t ad = st + (uint32_t)((ar + mi * 16) * 80 + ac * 2);
                ldm_x4(ah, ad);
                ldm_x4(al, ad + 10240);
#pragma unroll
                for (int nj = 0; nj < 8; nj++) {
                    mma_bf16(acc[mi][nj], ah, bh[nj]);
                    mma_bf16(acc[mi][nj], al, bh[nj]);
                    mma_bf16(acc[mi][nj], ah, bl[nj]);
                }
            }
        }
        __syncthreads();
        if (c <= 5) load_stage(c + 2, c & 1);
    }

#pragma unroll
    for (int mi = 0; mi < 4; mi++) {
        int rl = row0 + wm * 64 + mi * 16 + (lane >> 2);
        int rh = rl + 8;
#pragma unroll
        for (int nj = 0; nj < 8; nj++) {
            int col = n0 + wn * 64 + nj * 8 + (lane & 3) * 2;
            float b0 = __ldg(&bias[col]), b1 = __ldg(&bias[col + 1]);
            float v0 = acc[mi][nj][0] + b0, v1 = acc[mi][nj][1] + b1;
            float v2 = acc[mi][nj][2] + b0, v3 = acc[mi][nj][3] + b1;
            if (GELU) {
                v0 = 0.5f * v0 * (1.f + erff(v0 * 0.70710678118654752f));
                v1 = 0.5f * v1 * (1.f + erff(v1 * 0.70710678118654752f));
                v2 = 0.5f * v2 * (1.f + erff(v2 * 0.70710678118654752f));
                v3 = 0.5f * v3 * (1.f + erff(v3 * 0.70710678118654752f));
            }
            if (WF32) {
                if (rl < ROWS) *(float2*)(outF + (size_t)rl * ldo + col) = make_float2(v0, v1);
                if (rh < ROWS) *(float2*)(outF + (size_t)rh * ldo + col) = make_float2(v2, v3);
            }
            if (WSPLIT) {
                union { __nv_bfloat16 b[2]; uint32_t u; } h0, l0, h1, l1;
                split2(v0, h0.b[0], l0.b[0]); split2(v1, h0.b[1], l0.b[1]);
                split2(v2, h1.b[0], l1.b[0]); split2(v3, h1.b[1], l1.b[1]);
                if (rl < ROWS) {
                    *(uint32_t*)(outH + (size_t)rl * 256 + col) = h0.u;
                    *(uint32_t*)(outL + (size_t)rl * 256 + col) = l0.u;
                }
                if (rh < ROWS) {
                    *(uint32_t*)(outH + (size_t)rh * 256 + col) = h1.u;
                    *(uint32_t*)(outL + (size_t)rh * 256 + col) = l1.u;
                }
            }
        }
    }
}

// ---------------- launch -------------------------------------------------------
extern "C" void kernel_launch(void* const* d_in, const int* in_sizes, int n_in,
                              void* d_out, int out_size)
{
    const float* tgt       = (const float*)d_in[0];
    const float* query_pos = (const float*)d_in[1];
    const float* refpts    = (const float*)d_in[4];
    const float* src       = (const float*)d_in[6];
    const float* W_dsa = (const float*)d_in[10]; const float* b_dsa = (const float*)d_in[11];
    const float* g_nds = (const float*)d_in[12]; const float* b_nds = (const float*)d_in[13];
    const float* W_off = (const float*)d_in[14]; const float* b_off = (const float*)d_in[15];
    const float* W_att = (const float*)d_in[16]; const float* b_att = (const float*)d_in[17];
    const float* W_val = (const float*)d_in[18]; const float* b_val = (const float*)d_in[19];
    const float* W_out = (const float*)d_in[20]; const float* b_out = (const float*)d_in[21];
    const float* W_csa = (const float*)d_in[22]; const float* b_csa = (const float*)d_in[23];
    const float* g_n1  = (const float*)d_in[24]; const float* b_n1  = (const float*)d_in[25];
    const float* W_ff  = (const float*)d_in[26]; const float* b_ff  = (const float*)d_in[27];
    const float* g_n3  = (const float*)d_in[28]; const float* b_n3  = (const float*)d_in[29];
    float* out = (float*)d_out;

    float *buf0, *buf1, *buf2, *oa, *boa, *bcomb;
    __nv_bfloat16 *shi, *slo, *wth, *wtl, *woah, *woal;
    cudaGetSymbolAddress((void**)&buf0,  g_buf0);
    cudaGetSymbolAddress((void**)&buf1,  g_buf1);
    cudaGetSymbolAddress((void**)&buf2,  g_buf2);
    cudaGetSymbolAddress((void**)&oa,    g_oa);
    cudaGetSymbolAddress((void**)&boa,   g_boa);
    cudaGetSymbolAddress((void**)&bcomb, g_bcomb);
    cudaGetSymbolAddress((void**)&shi,   g_shi);
    cudaGetSymbolAddress((void**)&slo,   g_slo);
    cudaGetSymbolAddress((void**)&wth,   g_wt_hi);
    cudaGetSymbolAddress((void**)&wtl,   g_wt_lo);
    cudaGetSymbolAddress((void**)&woah,  g_woa_hi);
    cudaGetSymbolAddress((void**)&woal,  g_woa_lo);

    cudaFuncSetAttribute((const void*)mgemm_kernel<false, true,  false>,
                         cudaFuncAttributeMaxDynamicSharedMemorySize, GSMEM);
    cudaFuncSetAttribute((const void*)mgemm_kernel<true,  true,  false>,
                         cudaFuncAttributeMaxDynamicSharedMemorySize, GSMEM);

    const int MT  = (ROWS + 127) / 128;       // 235 row tiles
    const dim3 gFull(MT, 2);                  // N = 256
    const dim3 gOA  (MT, 1);                  // N = 128 (96 padded)
    const int EW4 = (ROWS * CDIM / 4 + 255) / 256;
    const int LNB = ROWS / 8;                 // 3750 warp-LN blocks

    // 0) combined weight + prep
    comb_kernel<<<256, 256>>>(W_out, W_csa, b_out, b_csa);
    prep_kernel<<<(PREP_TOT + 255) / 256, 256>>>(W_dsa, W_val, W_ff,
                                                 W_off, W_att, b_off, b_att);
    // 1) split src
    split_src_kernel<<<EW4, 256>>>(src, shi, slo);
    // 2) dsa GEMM -> buf0 (f32)
    mgemm_kernel<false, true, false><<<gFull, 128, GSMEM>>>(
        shi, slo, wth + 0 * 65536, wtl + 0 * 65536, b_dsa, buf0, 256, nullptr, nullptr);
    // 3) LN(nds) -> split
    ln_split_warp<<<LNB, 256>>>(buf0, g_nds, b_nds, shi, slo);
    // 4) value GEMM -> buf0 (f32)
    mgemm_kernel<false, true, false><<<gFull, 128, GSMEM>>>(
        shi, slo, wth + 1 * 65536, wtl + 1 * 65536, b_val, buf0, 256, nullptr, nullptr);
    // 5) q = tgt + query_pos -> split
    add_split_kernel<<<EW4, 256>>>(tgt, query_pos, shi, slo);
    // 6) offsets+attention GEMM (N=128 padded) -> oa
    mgemm_kernel<false, true, false><<<gOA, 128, GSMEM>>>(
        shi, slo, woah, woal, boa, oa, 128, nullptr, nullptr);
    // 7) deformable sampling -> split (shi/slo)
    msda_kernel<<<(ROWS * HEADS + 7) / 8, 256>>>(buf0, oa, refpts, shi, slo);
    // 8) combined out+csa GEMM -> buf1 (f32)
    mgemm_kernel<false, true, false><<<gFull, 128, GSMEM>>>(
        shi, slo, wth + 2 * 65536, wtl + 2 * 65536, bcomb, buf1, 256, nullptr, nullptr);
    // 9) t = LN(tgt + tgt2) -> buf2 (f32) + split
    addln_split_warp<<<LNB, 256>>>(tgt, buf1, g_n1, b_n1, buf2, shi, slo);
    // 10) ff = gelu(t @ W_ff + b_ff) -> buf0 (f32)
    mgemm_kernel<true, true, false><<<gFull, 128, GSMEM>>>(
        shi, slo, wth + 3 * 65536, wtl + 3 * 65536, b_ff, buf0, 256, nullptr, nullptr);
    // 11) out = LN(t + ff)
    addln_warp<<<LNB, 256>>>(buf2, buf0, g_n3, b_n3, out);
}

// round 8
// speedup vs baseline: 1.2051x; 1.1809x over previous
#include <cuda_runtime.h>
#include <cuda_fp16.h>
#include <cstdint>
#include <math.h>

// ---------------- problem constants ------------------------------------------
#define BATCH   2
#define LQ      15000
#define ROWS    (BATCH * LQ)      // 30000
#define CDIM    256
#define HEADS   8
#define HDIM    32
#define NPTS    4
#define HL      100
#define WL      150
#define LS      (HL * WL)

// ---------------- scratch ----------------------------------------------------
__device__ __align__(16) float   g_buf0[ROWS * CDIM];
__device__ __align__(16) float   g_buf1[ROWS * CDIM];
__device__ __align__(16) float   g_buf2[ROWS * CDIM];
__device__ __align__(16) float   g_oa  [ROWS * 128];
__device__ __align__(16) __half  g_sf16[ROWS * CDIM];          // fp16 activations
__device__ __align__(16) __half  g_wt_h16[4 * 65536];          // [w][n][k]: dsa,val,comb,ff
__device__ __align__(16) __half  g_wt_l16[4 * 65536];
__device__ __align__(16) __half  g_woa_h16[128 * 256];
__device__ __align__(16) __half  g_woa_l16[128 * 256];
__device__ __align__(16) float   g_boa[128];
__device__ __align__(16) float   g_wcomb[65536];               // W_out @ W_csa (fp32)
__device__ __align__(16) float   g_bcomb[256];

// ---------------- ptx helpers ------------------------------------------------
__device__ __forceinline__ uint32_t smem_u32(const void* p) {
    uint32_t a;
    asm("{ .reg .u64 t; cvta.to.shared.u64 t, %1; cvt.u32.u64 %0, t; }" : "=r"(a) : "l"(p));
    return a;
}
__device__ __forceinline__ void cpa16(uint32_t dst, const void* src, uint32_t sz) {
    asm volatile("cp.async.cg.shared.global [%0], [%1], 16, %2;"
                 :: "r"(dst), "l"(src), "r"(sz));
}
__device__ __forceinline__ void ldm_x4(uint32_t* r, uint32_t addr) {
    asm volatile("ldmatrix.sync.aligned.m8n8.x4.shared.b16 {%0,%1,%2,%3}, [%4];"
                 : "=r"(r[0]), "=r"(r[1]), "=r"(r[2]), "=r"(r[3]) : "r"(addr));
}
__device__ __forceinline__ void mma_f16(float* d, const uint32_t* a, const uint32_t* b) {
    asm volatile("mma.sync.aligned.m16n8k16.row.col.f32.f16.f16.f32 "
        "{%0,%1,%2,%3}, {%4,%5,%6,%7}, {%8,%9}, {%0,%1,%2,%3};"
        : "+f"(d[0]), "+f"(d[1]), "+f"(d[2]), "+f"(d[3])
        : "r"(a[0]), "r"(a[1]), "r"(a[2]), "r"(a[3]), "r"(b[0]), "r"(b[1]));
}

// ---------------- fp16 split helper ------------------------------------------
__device__ __forceinline__ void split2h(float x, __half& h, __half& l) {
    h = __float2half_rn(x);
    l = __float2half_rn(x - __half2float(h));
}

// ---------------- W_comb = W_out @ W_csa, b_comb = b_out @ W_csa + b_csa ------
__global__ void comb_kernel(const float* __restrict__ Wo, const float* __restrict__ Wc,
                            const float* __restrict__ bo, const float* __restrict__ bc)
{
    const int n = threadIdx.x;        // 0..255
    const int k = blockIdx.x;         // 0..255
    float s = 0.f;
#pragma unroll 8
    for (int j = 0; j < 256; j++) s = fmaf(Wo[k * 256 + j], Wc[j * 256 + n], s);
    g_wcomb[k * 256 + n] = s;
    if (k == 0) {
        float sb = 0.f;
#pragma unroll 8
        for (int j = 0; j < 256; j++) sb = fmaf(bo[j], Wc[j * 256 + n], sb);
        g_bcomb[n] = sb + bc[n];
    }
}

// ---------------- weight prep: transpose + fp16 split -------------------------
#define PREP_TOT (4 * 65536 + 128 * 256 + 128)
__global__ void prep_kernel(const float* __restrict__ Wd, const float* __restrict__ Wv,
                            const float* __restrict__ Wf, const float* __restrict__ Woff,
                            const float* __restrict__ Watt, const float* __restrict__ boff,
                            const float* __restrict__ batt)
{
    int idx = blockIdx.x * 256 + threadIdx.x;
    if (idx < 4 * 65536) {
        int w = idx >> 16, e = idx & 65535, n = e >> 8, k = e & 255;
        float v;
        if (w == 0)      v = Wd[k * 256 + n];
        else if (w == 1) v = Wv[k * 256 + n];
        else if (w == 2) v = g_wcomb[k * 256 + n];
        else             v = Wf[k * 256 + n];
        __half h, l; split2h(v, h, l);
        g_wt_h16[w * 65536 + n * 256 + k] = h;
        g_wt_l16[w * 65536 + n * 256 + k] = l;
    } else if (idx < 4 * 65536 + 128 * 256) {
        int e = idx - 4 * 65536, n = e >> 8, k = e & 255;
        float v = 0.f;
        if (n < 64)       v = Woff[k * 64 + n];
        else if (n < 96)  v = Watt[k * 32 + (n - 64)];
        __half h, l; split2h(v, h, l);
        g_woa_h16[n * 256 + k] = h;
        g_woa_l16[n * 256 + k] = l;
    } else if (idx < PREP_TOT) {
        int j = idx - (4 * 65536 + 128 * 256);
        g_boa[j] = (j < 64) ? boff[j] : (j < 96 ? batt[j - 64] : 0.f);
    }
}

// ---------------- elementwise conversion kernels ------------------------------
// 8 elements per thread
__global__ void cvt_f16_kernel(const float* __restrict__ x, __half* __restrict__ o)
{
    int base = (blockIdx.x * 256 + threadIdx.x) * 8;
    if (base >= ROWS * CDIM) return;
    float4 v0 = *(const float4*)(x + base);
    float4 v1 = *(const float4*)(x + base + 4);
    union { __half h[8]; uint4 u; } p;
    p.h[0] = __float2half_rn(v0.x); p.h[1] = __float2half_rn(v0.y);
    p.h[2] = __float2half_rn(v0.z); p.h[3] = __float2half_rn(v0.w);
    p.h[4] = __float2half_rn(v1.x); p.h[5] = __float2half_rn(v1.y);
    p.h[6] = __float2half_rn(v1.z); p.h[7] = __float2half_rn(v1.w);
    *(uint4*)(o + base) = p.u;
}

__global__ void add_f16_kernel(const float* __restrict__ a, const float* __restrict__ b,
                               __half* __restrict__ o)
{
    int base = (blockIdx.x * 256 + threadIdx.x) * 8;
    if (base >= ROWS * CDIM) return;
    float4 a0 = *(const float4*)(a + base), a1 = *(const float4*)(a + base + 4);
    float4 b0 = *(const float4*)(b + base), b1 = *(const float4*)(b + base + 4);
    union { __half h[8]; uint4 u; } p;
    p.h[0] = __float2half_rn(a0.x + b0.x); p.h[1] = __float2half_rn(a0.y + b0.y);
    p.h[2] = __float2half_rn(a0.z + b0.z); p.h[3] = __float2half_rn(a0.w + b0.w);
    p.h[4] = __float2half_rn(a1.x + b1.x); p.h[5] = __float2half_rn(a1.y + b1.y);
    p.h[6] = __float2half_rn(a1.z + b1.z); p.h[7] = __float2half_rn(a1.w + b1.w);
    *(uint4*)(o + base) = p.u;
}

// ---------------- warp-per-row layernorm kernels ------------------------------
__device__ __forceinline__ float warp_sum(float v)
{
#pragma unroll
    for (int o = 16; o > 0; o >>= 1) v += __shfl_xor_sync(0xffffffffu, v, o);
    return v;
}

// o = fp16(LN(x)*g+b)
__global__ void ln_f16_warp(const float* __restrict__ x, const float* __restrict__ g,
                            const float* __restrict__ b, __half* __restrict__ o)
{
    const int w = threadIdx.x >> 5, lane = threadIdx.x & 31;
    const int row = blockIdx.x * 8 + w;
    const float4* xr = (const float4*)(x + (size_t)row * 256) + lane * 2;
    float4 v0 = xr[0], v1 = xr[1];
    float vv[8] = {v0.x, v0.y, v0.z, v0.w, v1.x, v1.y, v1.z, v1.w};
    float s = 0.f;
#pragma unroll
    for (int i = 0; i < 8; i++) s += vv[i];
    float mean = warp_sum(s) * (1.f / 256);
    float va = 0.f;
#pragma unroll
    for (int i = 0; i < 8; i++) { vv[i] -= mean; va += vv[i] * vv[i]; }
    float rs = rsqrtf(warp_sum(va) * (1.f / 256) + 1e-5f);
    float4 g0 = ((const float4*)g)[lane * 2], g1 = ((const float4*)g)[lane * 2 + 1];
    float4 b0 = ((const float4*)b)[lane * 2], b1 = ((const float4*)b)[lane * 2 + 1];
    float gg[8] = {g0.x, g0.y, g0.z, g0.w, g1.x, g1.y, g1.z, g1.w};
    float bb[8] = {b0.x, b0.y, b0.z, b0.w, b1.x, b1.y, b1.z, b1.w};
    union { __half h[8]; uint4 u; } p;
#pragma unroll
    for (int i = 0; i < 8; i++) p.h[i] = __float2half_rn(vv[i] * rs * gg[i] + bb[i]);
    *(uint4*)(o + (size_t)row * 256 + lane * 8) = p.u;
}

// t = LN(a+c)*g+b -> y (f32) + fp16
__global__ void addln_f16_warp(const float* __restrict__ a, const float* __restrict__ c,
                               const float* __restrict__ g, const float* __restrict__ b,
                               float* __restrict__ y, __half* __restrict__ o)
{
    const int w = threadIdx.x >> 5, lane = threadIdx.x & 31;
    const int row = blockIdx.x * 8 + w;
    const float4* ar = (const float4*)(a + (size_t)row * 256) + lane * 2;
    const float4* cr = (const float4*)(c + (size_t)row * 256) + lane * 2;
    float4 a0 = ar[0], a1 = ar[1], c0 = cr[0], c1 = cr[1];
    float vv[8] = {a0.x + c0.x, a0.y + c0.y, a0.z + c0.z, a0.w + c0.w,
                   a1.x + c1.x, a1.y + c1.y, a1.z + c1.z, a1.w + c1.w};
    float s = 0.f;
#pragma unroll
    for (int i = 0; i < 8; i++) s += vv[i];
    float mean = warp_sum(s) * (1.f / 256);
    float va = 0.f;
#pragma unroll
    for (int i = 0; i < 8; i++) { vv[i] -= mean; va += vv[i] * vv[i]; }
    float rs = rsqrtf(warp_sum(va) * (1.f / 256) + 1e-5f);
    float4 g0 = ((const float4*)g)[lane * 2], g1 = ((const float4*)g)[lane * 2 + 1];
    float4 b0 = ((const float4*)b)[lane * 2], b1 = ((const float4*)b)[lane * 2 + 1];
    float gg[8] = {g0.x, g0.y, g0.z, g0.w, g1.x, g1.y, g1.z, g1.w};
    float bb[8] = {b0.x, b0.y, b0.z, b0.w, b1.x, b1.y, b1.z, b1.w};
    union { __half h[8]; uint4 u; } p;
    float out8[8];
#pragma unroll
    for (int i = 0; i < 8; i++) {
        float t = vv[i] * rs * gg[i] + bb[i];
        out8[i] = t;
        p.h[i] = __float2half_rn(t);
    }
    float4* yr = (float4*)(y + (size_t)row * 256) + lane * 2;
    yr[0] = make_float4(out8[0], out8[1], out8[2], out8[3]);
    yr[1] = make_float4(out8[4], out8[5], out8[6], out8[7]);
    *(uint4*)(o + (size_t)row * 256 + lane * 8) = p.u;
}

// y = LN(a+c)*g+b (f32 only)
__global__ void addln_warp(const float* __restrict__ a, const float* __restrict__ c,
                           const float* __restrict__ g, const float* __restrict__ b,
                           float* __restrict__ y)
{
    const int w = threadIdx.x >> 5, lane = threadIdx.x & 31;
    const int row = blockIdx.x * 8 + w;
    const float4* ar = (const float4*)(a + (size_t)row * 256) + lane * 2;
    const float4* cr = (const float4*)(c + (size_t)row * 256) + lane * 2;
    float4 a0 = ar[0], a1 = ar[1], c0 = cr[0], c1 = cr[1];
    float vv[8] = {a0.x + c0.x, a0.y + c0.y, a0.z + c0.z, a0.w + c0.w,
                   a1.x + c1.x, a1.y + c1.y, a1.z + c1.z, a1.w + c1.w};
    float s = 0.f;
#pragma unroll
    for (int i = 0; i < 8; i++) s += vv[i];
    float mean = warp_sum(s) * (1.f / 256);
    float va = 0.f;
#pragma unroll
    for (int i = 0; i < 8; i++) { vv[i] -= mean; va += vv[i] * vv[i]; }
    float rs = rsqrtf(warp_sum(va) * (1.f / 256) + 1e-5f);
    float4 g0 = ((const float4*)g)[lane * 2], g1 = ((const float4*)g)[lane * 2 + 1];
    float4 b0 = ((const float4*)b)[lane * 2], b1 = ((const float4*)b)[lane * 2 + 1];
    float gg[8] = {g0.x, g0.y, g0.z, g0.w, g1.x, g1.y, g1.z, g1.w};
    float bb[8] = {b0.x, b0.y, b0.z, b0.w, b1.x, b1.y, b1.z, b1.w};
    float out8[8];
#pragma unroll
    for (int i = 0; i < 8; i++) out8[i] = vv[i] * rs * gg[i] + bb[i];
    float4* yr = (float4*)(y + (size_t)row * 256) + lane * 2;
    yr[0] = make_float4(out8[0], out8[1], out8[2], out8[3]);
    yr[1] = make_float4(out8[4], out8[5], out8[6], out8[7]);
}

// ---------------- deformable sampling ----------------------------------------
__device__ __forceinline__ float fetch_v(const float* __restrict__ vbase, int x, int y)
{
    if (x < 0 || x >= WL || y < 0 || y >= HL) return 0.f;
    return vbase[(size_t)(y * WL + x) * CDIM];
}

__global__ void msda_kernel(const float* __restrict__ value, const float* __restrict__ oa,
                            const float* __restrict__ ref, __half* __restrict__ o)
{
    const int warp = blockIdx.x * (blockDim.x >> 5) + (threadIdx.x >> 5);
    const int lane = threadIdx.x & 31;
    if (warp >= ROWS * HEADS) return;
    const int hd = warp & 7;
    const int bq = warp >> 3;
    const int b  = bq / LQ;

    const float* oarow = oa + (size_t)bq * 128;
    float a0 = oarow[64 + hd * 4 + 0];
    float a1 = oarow[64 + hd * 4 + 1];
    float a2 = oarow[64 + hd * 4 + 2];
    float a3 = oarow[64 + hd * 4 + 3];
    float m  = fmaxf(fmaxf(a0, a1), fmaxf(a2, a3));
    float e0 = expf(a0 - m), e1 = expf(a1 - m), e2 = expf(a2 - m), e3 = expf(a3 - m);
    float inv = 1.f / (e0 + e1 + e2 + e3);
    float w[4] = {e0 * inv, e1 * inv, e2 * inv, e3 * inv};

    const float rx = ref[(size_t)bq * 2 + 0];
    const float ry = ref[(size_t)bq * 2 + 1];
    const float* vbase = value + (size_t)b * LS * CDIM + hd * HDIM + lane;

    float acc = 0.f;
#pragma unroll
    for (int p = 0; p < NPTS; p++) {
        float ox = oarow[hd * 8 + p * 2 + 0];
        float oy = oarow[hd * 8 + p * 2 + 1];
        float X = (rx + ox / (float)WL) * (float)WL - 0.5f;
        float Y = (ry + oy / (float)HL) * (float)HL - 0.5f;
        float x0f = floorf(X), y0f = floorf(Y);
        float lx = X - x0f, ly = Y - y0f;
        int x0 = (int)x0f, y0 = (int)y0f;
        float s00 = fetch_v(vbase, x0,     y0);
        float s10 = fetch_v(vbase, x0 + 1, y0);
        float s01 = fetch_v(vbase, x0,     y0 + 1);
        float s11 = fetch_v(vbase, x0 + 1, y0 + 1);
        float sv  = s00 * (1.f - lx) * (1.f - ly) + s10 * lx * (1.f - ly)
                  + s01 * (1.f - lx) * ly         + s11 * lx * ly;
        acc = fmaf(w[p], sv, acc);
    }
    o[(size_t)bq * CDIM + hd * HDIM + lane] = __float2half_rn(acc);
}

// ---------------- mma.sync fp16 GEMM (128 threads, 4 warps, 64x64 tiles) ------
// C[ROWS, N] = A16 @ (Wh + Wl)^T + bias   (W stored [n][k], K contiguous)
// 2-term: A*Wh + A*Wl.  BM=128 BN=128 BK=32, 2-stage cp.async, 2 CTAs/SM.
// smem per stage: A, Bh, Bl each 128 rows x 40 fp16 (80B stride) = 10240 B.
#define GSTAGE 30720
#define GSMEM  (2 * GSTAGE)

template<bool GELU>
__global__ void __launch_bounds__(128, 2) mgemm_kernel(
    const __half* __restrict__ A,
    const __half* __restrict__ Bh, const __half* __restrict__ Bl,
    const float* __restrict__ bias,
    float* __restrict__ outF, int ldo)
{
    extern __shared__ __align__(128) char smem[];
    const int tid = threadIdx.x, lane = tid & 31, wid = tid >> 5;
    const int row0 = blockIdx.x * 128, n0 = blockIdx.y * 128;
    const int wm = wid >> 1, wn = wid & 1;           // 2 x 2 warp grid
    const uint32_t sbase = smem_u32(smem);

    float acc[4][8][4];
#pragma unroll
    for (int i = 0; i < 4; i++)
#pragma unroll
        for (int j = 0; j < 8; j++)
#pragma unroll
            for (int q = 0; q < 4; q++) acc[i][j][q] = 0.f;

    auto load_stage = [&](int c, int s) {
        const int kk = c * 32;
        const uint32_t st = sbase + s * GSTAGE;
#pragma unroll
        for (int i = 0; i < 4; i++) {
            int g = i * 128 + tid;                   // 0..511 granules per matrix
            int r = g >> 2, cc = g & 3;
            uint32_t so = (uint32_t)(r * 80 + cc * 16);
            int gr = row0 + r;
            uint32_t sz = (gr < ROWS) ? 16u : 0u;
            cpa16(st + so,         A  + (size_t)gr * 256 + kk + cc * 8, sz);
            cpa16(st + 10240 + so, Bh + (size_t)(n0 + r) * 256 + kk + cc * 8, 16u);
            cpa16(st + 20480 + so, Bl + (size_t)(n0 + r) * 256 + kk + cc * 8, 16u);
        }
        asm volatile("cp.async.commit_group;" ::: "memory");
    };

    load_stage(0, 0);
    load_stage(1, 1);

#pragma unroll 1
    for (int c = 0; c < 8; c++) {
        if (c < 7) asm volatile("cp.async.wait_group 1;" ::: "memory");
        else       asm volatile("cp.async.wait_group 0;" ::: "memory");
        __syncthreads();

        const uint32_t st = sbase + (c & 1) * GSTAGE;
#pragma unroll
        for (int k16 = 0; k16 < 2; k16++) {
            uint32_t bh[8][2], bl[8][2];
            {
                int br = wn * 64 + ((lane >> 4) << 3) + (lane & 7);
                int bc = k16 * 16 + ((lane >> 3) & 1) * 8;
#pragma unroll
                for (int p = 0; p < 4; p++) {
                    uint32_t bd = st + 10240 + (uint32_t)((br + p * 16) * 80 + bc * 2);
                    uint32_t t4[4];
                    ldm_x4(t4, bd);
                    bh[2 * p][0] = t4[0]; bh[2 * p][1] = t4[1];
                    bh[2 * p + 1][0] = t4[2]; bh[2 * p + 1][1] = t4[3];
                    ldm_x4(t4, bd + 10240);
                    bl[2 * p][0] = t4[0]; bl[2 * p][1] = t4[1];
                    bl[2 * p + 1][0] = t4[2]; bl[2 * p + 1][1] = t4[3];
                }
            }
            int ar = wm * 64 + (lane & 15);
            int ac = k16 * 16 + ((lane >> 4) << 3);
#pragma unroll
            for (int mi = 0; mi < 4; mi++) {
                uint32_t ah[4];
                uint32_t ad = st + (uint32_t)((ar + mi * 16) * 80 + ac * 2);
                ldm_x4(ah, ad);
#pragma unroll
                for (int nj = 0; nj < 8; nj++) {
                    mma_f16(acc[mi][nj], ah, bh[nj]);
                    mma_f16(acc[mi][nj], ah, bl[nj]);
                }
            }
        }
        __syncthreads();
        if (c <= 5) load_stage(c + 2, c & 1);
    }

#pragma unroll
    for (int mi = 0; mi < 4; mi++) {
        int rl = row0 + wm * 64 + mi * 16 + (lane >> 2);
        int rh = rl + 8;
#pragma unroll
        for (int nj = 0; nj < 8; nj++) {
            int col = n0 + wn * 64 + nj * 8 + (lane & 3) * 2;
            float b0 = __ldg(&bias[col]), b1 = __ldg(&bias[col + 1]);
            float v0 = acc[mi][nj][0] + b0, v1 = acc[mi][nj][1] + b1;
            float v2 = acc[mi][nj][2] + b0, v3 = acc[mi][nj][3] + b1;
            if (GELU) {
                v0 = 0.5f * v0 * (1.f + erff(v0 * 0.70710678118654752f));
                v1 = 0.5f * v1 * (1.f + erff(v1 * 0.70710678118654752f));
                v2 = 0.5f * v2 * (1.f + erff(v2 * 0.70710678118654752f));
                v3 = 0.5f * v3 * (1.f + erff(v3 * 0.70710678118654752f));
            }
            if (rl < ROWS) *(float2*)(outF + (size_t)rl * ldo + col) = make_float2(v0, v1);
            if (rh < ROWS) *(float2*)(outF + (size_t)rh * ldo + col) = make_float2(v2, v3);
        }
    }
}

// ---------------- launch -------------------------------------------------------
extern "C" void kernel_launch(void* const* d_in, const int* in_sizes, int n_in,
                              void* d_out, int out_size)
{
    const float* tgt       = (const float*)d_in[0];
    const float* query_pos = (const float*)d_in[1];
    const float* refpts    = (const float*)d_in[4];
    const float* src       = (const float*)d_in[6];
    const float* W_dsa = (const float*)d_in[10]; const float* b_dsa = (const float*)d_in[11];
    const float* g_nds = (const float*)d_in[12]; const float* b_nds = (const float*)d_in[13];
    const float* W_off = (const float*)d_in[14]; const float* b_off = (const float*)d_in[15];
    const float* W_att = (const float*)d_in[16]; const float* b_att = (const float*)d_in[17];
    const float* W_val = (const float*)d_in[18]; const float* b_val = (const float*)d_in[19];
    const float* W_out = (const float*)d_in[20]; const float* b_out = (const float*)d_in[21];
    const float* W_csa = (const float*)d_in[22]; const float* b_csa = (const float*)d_in[23];
    const float* g_n1  = (const float*)d_in[24]; const float* b_n1  = (const float*)d_in[25];
    const float* W_ff  = (const float*)d_in[26]; const float* b_ff  = (const float*)d_in[27];
    const float* g_n3  = (const float*)d_in[28]; const float* b_n3  = (const float*)d_in[29];
    float* out = (float*)d_out;

    float *buf0, *buf1, *buf2, *oa, *boa, *bcomb;
    __half *sf16, *wth, *wtl, *woah, *woal;
    cudaGetSymbolAddress((void**)&buf0,  g_buf0);
    cudaGetSymbolAddress((void**)&buf1,  g_buf1);
    cudaGetSymbolAddress((void**)&buf2,  g_buf2);
    cudaGetSymbolAddress((void**)&oa,    g_oa);
    cudaGetSymbolAddress((void**)&boa,   g_boa);
    cudaGetSymbolAddress((void**)&bcomb, g_bcomb);
    cudaGetSymbolAddress((void**)&sf16,  g_sf16);
    cudaGetSymbolAddress((void**)&wth,   g_wt_h16);
    cudaGetSymbolAddress((void**)&wtl,   g_wt_l16);
    cudaGetSymbolAddress((void**)&woah,  g_woa_h16);
    cudaGetSymbolAddress((void**)&woal,  g_woa_l16);

    cudaFuncSetAttribute((const void*)mgemm_kernel<false>,
                         cudaFuncAttributeMaxDynamicSharedMemorySize, GSMEM);
    cudaFuncSetAttribute((const void*)mgemm_kernel<true>,
                         cudaFuncAttributeMaxDynamicSharedMemorySize, GSMEM);

    const int MT  = (ROWS + 127) / 128;       // 235 row tiles
    const dim3 gFull(MT, 2);                  // N = 256
    const dim3 gOA  (MT, 1);                  // N = 128 (96 padded)
    const int EW8 = (ROWS * CDIM / 8 + 255) / 256;
    const int LNB = ROWS / 8;                 // 3750 warp-LN blocks

    // 0) combined weight + prep
    comb_kernel<<<256, 256>>>(W_out, W_csa, b_out, b_csa);
    prep_kernel<<<(PREP_TOT + 255) / 256, 256>>>(W_dsa, W_val, W_ff,
                                                 W_off, W_att, b_off, b_att);
    // 1) src -> fp16
    cvt_f16_kernel<<<EW8, 256>>>(src, sf16);
    // 2) dsa GEMM -> buf0 (f32)
    mgemm_kernel<false><<<gFull, 128, GSMEM>>>(
        sf16, wth + 0 * 65536, wtl + 0 * 65536, b_dsa, buf0, 256);
    // 3) LN(nds) -> fp16
    ln_f16_warp<<<LNB, 256>>>(buf0, g_nds, b_nds, sf16);
    // 4) value GEMM -> buf0 (f32)
    mgemm_kernel<false><<<gFull, 128, GSMEM>>>(
        sf16, wth + 1 * 65536, wtl + 1 * 65536, b_val, buf0, 256);
    // 5) q = tgt + query_pos -> fp16
    add_f16_kernel<<<EW8, 256>>>(tgt, query_pos, sf16);
    // 6) offsets+attention GEMM (N=128 padded) -> oa
    mgemm_kernel<false><<<gOA, 128, GSMEM>>>(
        sf16, woah, woal, boa, oa, 128);
    // 7) deformable sampling -> fp16 (sf16)
    msda_kernel<<<(ROWS * HEADS + 7) / 8, 256>>>(buf0, oa, refpts, sf16);
    // 8) combined out+csa GEMM -> buf1 (f32)
    mgemm_kernel<false><<<gFull, 128, GSMEM>>>(
        sf16, wth + 2 * 65536, wtl + 2 * 65536, bcomb, buf1, 256);
    // 9) t = LN(tgt + tgt2) -> buf2 (f32) + fp16
    addln_f16_warp<<<LNB, 256>>>(tgt, buf1, g_n1, b_n1, buf2, sf16);
    // 10) ff = gelu(t @ W_ff + b_ff) -> buf0 (f32)
    mgemm_kernel<true><<<gFull, 128, GSMEM>>>(
        sf16, wth + 3 * 65536, wtl + 3 * 65536, b_ff, buf0, 256);
    // 11) out = LN(t + ff)
    addln_warp<<<LNB, 256>>>(buf2, buf0, g_n3, b_n3, out);
}

// round 9
// speedup vs baseline: 1.4374x; 1.1928x over previous
#include <cuda_runtime.h>
#include <cuda_fp16.h>
#include <cstdint>
#include <math.h>

// ---------------- problem constants ------------------------------------------
#define BATCH   2
#define LQ      15000
#define ROWS    (BATCH * LQ)      // 30000
#define CDIM    256
#define HEADS   8
#define HDIM    32
#define NPTS    4
#define HL      100
#define WL      150
#define LS      (HL * WL)

// ---------------- scratch ----------------------------------------------------
__device__ __align__(16) float   g_buf0[ROWS * CDIM];
__device__ __align__(16) float   g_buf1[ROWS * CDIM];
__device__ __align__(16) float   g_buf2[ROWS * CDIM];
__device__ __align__(16) float   g_oa  [ROWS * 128];
__device__ __align__(16) __half  g_sf16[ROWS * CDIM];          // fp16 activations
__device__ __align__(16) __half  g_wt_h16[4 * 65536];          // [w][n][k]: dsa,val,comb,ff
__device__ __align__(16) __half  g_woa_h16[128 * 256];
__device__ __align__(16) float   g_boa[128];
__device__ __align__(16) float   g_wcomb[65536];               // W_out @ W_csa (fp32)
__device__ __align__(16) float   g_bcomb[256];

// ---------------- ptx helpers ------------------------------------------------
__device__ __forceinline__ uint32_t smem_u32(const void* p) {
    uint32_t a;
    asm("{ .reg .u64 t; cvta.to.shared.u64 t, %1; cvt.u32.u64 %0, t; }" : "=r"(a) : "l"(p));
    return a;
}
__device__ __forceinline__ void cpa16(uint32_t dst, const void* src, uint32_t sz) {
    asm volatile("cp.async.cg.shared.global [%0], [%1], 16, %2;"
                 :: "r"(dst), "l"(src), "r"(sz));
}
__device__ __forceinline__ void ldm_x4(uint32_t* r, uint32_t addr) {
    asm volatile("ldmatrix.sync.aligned.m8n8.x4.shared.b16 {%0,%1,%2,%3}, [%4];"
                 : "=r"(r[0]), "=r"(r[1]), "=r"(r[2]), "=r"(r[3]) : "r"(addr));
}
__device__ __forceinline__ void mma_f16(float* d, const uint32_t* a, const uint32_t* b) {
    asm volatile("mma.sync.aligned.m16n8k16.row.col.f32.f16.f16.f32 "
        "{%0,%1,%2,%3}, {%4,%5,%6,%7}, {%8,%9}, {%0,%1,%2,%3};"
        : "+f"(d[0]), "+f"(d[1]), "+f"(d[2]), "+f"(d[3])
        : "r"(a[0]), "r"(a[1]), "r"(a[2]), "r"(a[3]), "r"(b[0]), "r"(b[1]));
}

// ---------------- W_comb = W_out @ W_csa, b_comb = b_out @ W_csa + b_csa ------
__global__ void comb_kernel(const float* __restrict__ Wo, const float* __restrict__ Wc,
                            const float* __restrict__ bo, const float* __restrict__ bc)
{
    const int n = threadIdx.x;        // 0..255
    const int k = blockIdx.x;         // 0..255
    float s = 0.f;
#pragma unroll 8
    for (int j = 0; j < 256; j++) s = fmaf(Wo[k * 256 + j], Wc[j * 256 + n], s);
    g_wcomb[k * 256 + n] = s;
    if (k == 0) {
        float sb = 0.f;
#pragma unroll 8
        for (int j = 0; j < 256; j++) sb = fmaf(bo[j], Wc[j * 256 + n], sb);
        g_bcomb[n] = sb + bc[n];
    }
}

// ---------------- weight prep: transpose + fp16 -------------------------------
#define PREP_TOT (4 * 65536 + 128 * 256 + 128)
__global__ void prep_kernel(const float* __restrict__ Wd, const float* __restrict__ Wv,
                            const float* __restrict__ Wf, const float* __restrict__ Woff,
                            const float* __restrict__ Watt, const float* __restrict__ boff,
                            const float* __restrict__ batt)
{
    int idx = blockIdx.x * 256 + threadIdx.x;
    if (idx < 4 * 65536) {
        int w = idx >> 16, e = idx & 65535, n = e >> 8, k = e & 255;
        float v;
        if (w == 0)      v = Wd[k * 256 + n];
        else if (w == 1) v = Wv[k * 256 + n];
        else if (w == 2) v = g_wcomb[k * 256 + n];
        else             v = Wf[k * 256 + n];
        g_wt_h16[w * 65536 + n * 256 + k] = __float2half_rn(v);
    } else if (idx < 4 * 65536 + 128 * 256) {
        int e = idx - 4 * 65536, n = e >> 8, k = e & 255;
        float v = 0.f;
        if (n < 64)       v = Woff[k * 64 + n];
        else if (n < 96)  v = Watt[k * 32 + (n - 64)];
        g_woa_h16[n * 256 + k] = __float2half_rn(v);
    } else if (idx < PREP_TOT) {
        int j = idx - (4 * 65536 + 128 * 256);
        g_boa[j] = (j < 64) ? boff[j] : (j < 96 ? batt[j - 64] : 0.f);
    }
}

// ---------------- elementwise conversion kernels ------------------------------
__global__ void cvt_f16_kernel(const float* __restrict__ x, __half* __restrict__ o)
{
    int base = (blockIdx.x * 256 + threadIdx.x) * 8;
    if (base >= ROWS * CDIM) return;
    float4 v0 = *(const float4*)(x + base);
    float4 v1 = *(const float4*)(x + base + 4);
    union { __half h[8]; uint4 u; } p;
    p.h[0] = __float2half_rn(v0.x); p.h[1] = __float2half_rn(v0.y);
    p.h[2] = __float2half_rn(v0.z); p.h[3] = __float2half_rn(v0.w);
    p.h[4] = __float2half_rn(v1.x); p.h[5] = __float2half_rn(v1.y);
    p.h[6] = __float2half_rn(v1.z); p.h[7] = __float2half_rn(v1.w);
    *(uint4*)(o + base) = p.u;
}

__global__ void add_f16_kernel(const float* __restrict__ a, const float* __restrict__ b,
                               __half* __restrict__ o)
{
    int base = (blockIdx.x * 256 + threadIdx.x) * 8;
    if (base >= ROWS * CDIM) return;
    float4 a0 = *(const float4*)(a + base), a1 = *(const float4*)(a + base + 4);
    float4 b0 = *(const float4*)(b + base), b1 = *(const float4*)(b + base + 4);
    union { __half h[8]; uint4 u; } p;
    p.h[0] = __float2half_rn(a0.x + b0.x); p.h[1] = __float2half_rn(a0.y + b0.y);
    p.h[2] = __float2half_rn(a0.z + b0.z); p.h[3] = __float2half_rn(a0.w + b0.w);
    p.h[4] = __float2half_rn(a1.x + b1.x); p.h[5] = __float2half_rn(a1.y + b1.y);
    p.h[6] = __float2half_rn(a1.z + b1.z); p.h[7] = __float2half_rn(a1.w + b1.w);
    *(uint4*)(o + base) = p.u;
}

// ---------------- warp-per-row layernorm kernels ------------------------------
__device__ __forceinline__ float warp_sum(float v)
{
#pragma unroll
    for (int o = 16; o > 0; o >>= 1) v += __shfl_xor_sync(0xffffffffu, v, o);
    return v;
}

__global__ void ln_f16_warp(const float* __restrict__ x, const float* __restrict__ g,
                            const float* __restrict__ b, __half* __restrict__ o)
{
    const int w = threadIdx.x >> 5, lane = threadIdx.x & 31;
    const int row = blockIdx.x * 8 + w;
    const float4* xr = (const float4*)(x + (size_t)row * 256) + lane * 2;
    float4 v0 = xr[0], v1 = xr[1];
    float vv[8] = {v0.x, v0.y, v0.z, v0.w, v1.x, v1.y, v1.z, v1.w};
    float s = 0.f;
#pragma unroll
    for (int i = 0; i < 8; i++) s += vv[i];
    float mean = warp_sum(s) * (1.f / 256);
    float va = 0.f;
#pragma unroll
    for (int i = 0; i < 8; i++) { vv[i] -= mean; va += vv[i] * vv[i]; }
    float rs = rsqrtf(warp_sum(va) * (1.f / 256) + 1e-5f);
    float4 g0 = ((const float4*)g)[lane * 2], g1 = ((const float4*)g)[lane * 2 + 1];
    float4 b0 = ((const float4*)b)[lane * 2], b1 = ((const float4*)b)[lane * 2 + 1];
    float gg[8] = {g0.x, g0.y, g0.z, g0.w, g1.x, g1.y, g1.z, g1.w};
    float bb[8] = {b0.x, b0.y, b0.z, b0.w, b1.x, b1.y, b1.z, b1.w};
    union { __half h[8]; uint4 u; } p;
#pragma unroll
    for (int i = 0; i < 8; i++) p.h[i] = __float2half_rn(vv[i] * rs * gg[i] + bb[i]);
    *(uint4*)(o + (size_t)row * 256 + lane * 8) = p.u;
}

__global__ void addln_f16_warp(const float* __restrict__ a, const float* __restrict__ c,
                               const float* __restrict__ g, const float* __restrict__ b,
                               float* __restrict__ y, __half* __restrict__ o)
{
    const int w = threadIdx.x >> 5, lane = threadIdx.x & 31;
    const int row = blockIdx.x * 8 + w;
    const float4* ar = (const float4*)(a + (size_t)row * 256) + lane * 2;
    const float4* cr = (const float4*)(c + (size_t)row * 256) + lane * 2;
    float4 a0 = ar[0], a1 = ar[1], c0 = cr[0], c1 = cr[1];
    float vv[8] = {a0.x + c0.x, a0.y + c0.y, a0.z + c0.z, a0.w + c0.w,
                   a1.x + c1.x, a1.y + c1.y, a1.z + c1.z, a1.w + c1.w};
    float s = 0.f;
#pragma unroll
    for (int i = 0; i < 8; i++) s += vv[i];
    float mean = warp_sum(s) * (1.f / 256);
    float va = 0.f;
#pragma unroll
    for (int i = 0; i < 8; i++) { vv[i] -= mean; va += vv[i] * vv[i]; }
    float rs = rsqrtf(warp_sum(va) * (1.f / 256) + 1e-5f);
    float4 g0 = ((const float4*)g)[lane * 2], g1 = ((const float4*)g)[lane * 2 + 1];
    float4 b0 = ((const float4*)b)[lane * 2], b1 = ((const float4*)b)[lane * 2 + 1];
    float gg[8] = {g0.x, g0.y, g0.z, g0.w, g1.x, g1.y, g1.z, g1.w};
    float bb[8] = {b0.x, b0.y, b0.z, b0.w, b1.x, b1.y, b1.z, b1.w};
    union { __half h[8]; uint4 u; } p;
    float out8[8];
#pragma unroll
    for (int i = 0; i < 8; i++) {
        float t = vv[i] * rs * gg[i] + bb[i];
        out8[i] = t;
        p.h[i] = __float2half_rn(t);
    }
    float4* yr = (float4*)(y + (size_t)row * 256) + lane * 2;
    yr[0] = make_float4(out8[0], out8[1], out8[2], out8[3]);
    yr[1] = make_float4(out8[4], out8[5], out8[6], out8[7]);
    *(uint4*)(o + (size_t)row * 256 + lane * 8) = p.u;
}

__global__ void addln_warp(const float* __restrict__ a, const float* __restrict__ c,
                           const float* __restrict__ g, const float* __restrict__ b,
                           float* __restrict__ y)
{
    const int w = threadIdx.x >> 5, lane = threadIdx.x & 31;
    const int row = blockIdx.x * 8 + w;
    const float4* ar = (const float4*)(a + (size_t)row * 256) + lane * 2;
    const float4* cr = (const float4*)(c + (size_t)row * 256) + lane * 2;
    float4 a0 = ar[0], a1 = ar[1], c0 = cr[0], c1 = cr[1];
    float vv[8] = {a0.x + c0.x, a0.y + c0.y, a0.z + c0.z, a0.w + c0.w,
                   a1.x + c1.x, a1.y + c1.y, a1.z + c1.z, a1.w + c1.w};
    float s = 0.f;
#pragma unroll
    for (int i = 0; i < 8; i++) s += vv[i];
    float mean = warp_sum(s) * (1.f / 256);
    float va = 0.f;
#pragma unroll
    for (int i = 0; i < 8; i++) { vv[i] -= mean; va += vv[i] * vv[i]; }
    float rs = rsqrtf(warp_sum(va) * (1.f / 256) + 1e-5f);
    float4 g0 = ((const float4*)g)[lane * 2], g1 = ((const float4*)g)[lane * 2 + 1];
    float4 b0 = ((const float4*)b)[lane * 2], b1 = ((const float4*)b)[lane * 2 + 1];
    float gg[8] = {g0.x, g0.y, g0.z, g0.w, g1.x, g1.y, g1.z, g1.w};
    float bb[8] = {b0.x, b0.y, b0.z, b0.w, b1.x, b1.y, b1.z, b1.w};
    float out8[8];
#pragma unroll
    for (int i = 0; i < 8; i++) out8[i] = vv[i] * rs * gg[i] + bb[i];
    float4* yr = (float4*)(y + (size_t)row * 256) + lane * 2;
    yr[0] = make_float4(out8[0], out8[1], out8[2], out8[3]);
    yr[1] = make_float4(out8[4], out8[5], out8[6], out8[7]);
}

// ---------------- deformable sampling ----------------------------------------
__device__ __forceinline__ float fetch_v(const float* __restrict__ vbase, int x, int y)
{
    if (x < 0 || x >= WL || y < 0 || y >= HL) return 0.f;
    return vbase[(size_t)(y * WL + x) * CDIM];
}

__global__ void msda_kernel(const float* __restrict__ value, const float* __restrict__ oa,
                            const float* __restrict__ ref, __half* __restrict__ o)
{
    const int warp = blockIdx.x * (blockDim.x >> 5) + (threadIdx.x >> 5);
    const int lane = threadIdx.x & 31;
    if (warp >= ROWS * HEADS) return;
    const int hd = warp & 7;
    const int bq = warp >> 3;
    const int b  = bq / LQ;

    const float* oarow = oa + (size_t)bq * 128;
    float a0 = oarow[64 + hd * 4 + 0];
    float a1 = oarow[64 + hd * 4 + 1];
    float a2 = oarow[64 + hd * 4 + 2];
    float a3 = oarow[64 + hd * 4 + 3];
    float m  = fmaxf(fmaxf(a0, a1), fmaxf(a2, a3));
    float e0 = expf(a0 - m), e1 = expf(a1 - m), e2 = expf(a2 - m), e3 = expf(a3 - m);
    float inv = 1.f / (e0 + e1 + e2 + e3);
    float w[4] = {e0 * inv, e1 * inv, e2 * inv, e3 * inv};

    const float rx = ref[(size_t)bq * 2 + 0];
    const float ry = ref[(size_t)bq * 2 + 1];
    const float* vbase = value + (size_t)b * LS * CDIM + hd * HDIM + lane;

    float acc = 0.f;
#pragma unroll
    for (int p = 0; p < NPTS; p++) {
        float ox = oarow[hd * 8 + p * 2 + 0];
        float oy = oarow[hd * 8 + p * 2 + 1];
        float X = (rx + ox / (float)WL) * (float)WL - 0.5f;
        float Y = (ry + oy / (float)HL) * (float)HL - 0.5f;
        float x0f = floorf(X), y0f = floorf(Y);
        float lx = X - x0f, ly = Y - y0f;
        int x0 = (int)x0f, y0 = (int)y0f;
        float s00 = fetch_v(vbase, x0,     y0);
        float s10 = fetch_v(vbase, x0 + 1, y0);
        float s01 = fetch_v(vbase, x0,     y0 + 1);
        float s11 = fetch_v(vbase, x0 + 1, y0 + 1);
        float sv  = s00 * (1.f - lx) * (1.f - ly) + s10 * lx * (1.f - ly)
                  + s01 * (1.f - lx) * ly         + s11 * lx * ly;
        acc = fmaf(w[p], sv, acc);
    }
    o[(size_t)bq * CDIM + hd * HDIM + lane] = __float2half_rn(acc);
}

// ---------------- mma.sync fp16 GEMM (128 threads, 4 warps, 64x64 tiles) ------
// C[ROWS, N] = A16 @ Wh^T + bias   (W stored [n][k], K contiguous)
// Single term.  BM=128 BN=128 BK=32, 2-stage cp.async, 2 CTAs/SM.
// smem per stage: A, B each 128 rows x 40 fp16 (80B stride) = 10240 B.
#define GSTAGE 20480
#define GSMEM  (2 * GSTAGE)

template<bool GELU>
__global__ void __launch_bounds__(128, 2) mgemm_kernel(
    const __half* __restrict__ A, const __half* __restrict__ Bh,
    const float* __restrict__ bias,
    float* __restrict__ outF, int ldo)
{
    extern __shared__ __align__(128) char smem[];
    const int tid = threadIdx.x, lane = tid & 31, wid = tid >> 5;
    const int row0 = blockIdx.x * 128, n0 = blockIdx.y * 128;
    const int wm = wid >> 1, wn = wid & 1;           // 2 x 2 warp grid
    const uint32_t sbase = smem_u32(smem);

    float acc[4][8][4];
#pragma unroll
    for (int i = 0; i < 4; i++)
#pragma unroll
        for (int j = 0; j < 8; j++)
#pragma unroll
            for (int q = 0; q < 4; q++) acc[i][j][q] = 0.f;

    auto load_stage = [&](int c, int s) {
        const int kk = c * 32;
        const uint32_t st = sbase + s * GSTAGE;
#pragma unroll
        for (int i = 0; i < 4; i++) {
            int g = i * 128 + tid;                   // 0..511 granules per matrix
            int r = g >> 2, cc = g & 3;
            uint32_t so = (uint32_t)(r * 80 + cc * 16);
            int gr = row0 + r;
            uint32_t sz = (gr < ROWS) ? 16u : 0u;
            cpa16(st + so,         A  + (size_t)gr * 256 + kk + cc * 8, sz);
            cpa16(st + 10240 + so, Bh + (size_t)(n0 + r) * 256 + kk + cc * 8, 16u);
        }
        asm volatile("cp.async.commit_group;" ::: "memory");
    };

    load_stage(0, 0);
    load_stage(1, 1);

#pragma unroll 1
    for (int c = 0; c < 8; c++) {
        if (c < 7) asm volatile("cp.async.wait_group 1;" ::: "memory");
        else       asm volatile("cp.async.wait_group 0;" ::: "memory");
        __syncthreads();

        const uint32_t st = sbase + (c & 1) * GSTAGE;
#pragma unroll
        for (int k16 = 0; k16 < 2; k16++) {
            uint32_t bh[8][2];
            {
                int br = wn * 64 + ((lane >> 4) << 3) + (lane & 7);
                int bc = k16 * 16 + ((lane >> 3) & 1) * 8;
#pragma unroll
                for (int p = 0; p < 4; p++) {
                    uint32_t bd = st + 10240 + (uint32_t)((br + p * 16) * 80 + bc * 2);
                    uint32_t t4[4];
                    ldm_x4(t4, bd);
                    bh[2 * p][0] = t4[0]; bh[2 * p][1] = t4[1];
                    bh[2 * p + 1][0] = t4[2]; bh[2 * p + 1][1] = t4[3];
                }
            }
            int ar = wm * 64 + (lane & 15);
            int ac = k16 * 16 + ((lane >> 4) << 3);
#pragma unroll
            for (int mi = 0; mi < 4; mi++) {
                uint32_t ah[4];
                uint32_t ad = st + (uint32_t)((ar + mi * 16) * 80 + ac * 2);
                ldm_x4(ah, ad);
#pragma unroll
                for (int nj = 0; nj < 8; nj++)
                    mma_f16(acc[mi][nj], ah, bh[nj]);
            }
        }
        __syncthreads();
        if (c <= 5) load_stage(c + 2, c & 1);
    }

#pragma unroll
    for (int mi = 0; mi < 4; mi++) {
        int rl = row0 + wm * 64 + mi * 16 + (lane >> 2);
        int rh = rl + 8;
#pragma unroll
        for (int nj = 0; nj < 8; nj++) {
            int col = n0 + wn * 64 + nj * 8 + (lane & 3) * 2;
            float b0 = __ldg(&bias[col]), b1 = __ldg(&bias[col + 1]);
            float v0 = acc[mi][nj][0] + b0, v1 = acc[mi][nj][1] + b1;
            float v2 = acc[mi][nj][2] + b0, v3 = acc[mi][nj][3] + b1;
            if (GELU) {
                v0 = 0.5f * v0 * (1.f + erff(v0 * 0.70710678118654752f));
                v1 = 0.5f * v1 * (1.f + erff(v1 * 0.70710678118654752f));
                v2 = 0.5f * v2 * (1.f + erff(v2 * 0.70710678118654752f));
                v3 = 0.5f * v3 * (1.f + erff(v3 * 0.70710678118654752f));
            }
            if (rl < ROWS) *(float2*)(outF + (size_t)rl * ldo + col) = make_float2(v0, v1);
            if (rh < ROWS) *(float2*)(outF + (size_t)rh * ldo + col) = make_float2(v2, v3);
        }
    }
}

// ---------------- launch -------------------------------------------------------
extern "C" void kernel_launch(void* const* d_in, const int* in_sizes, int n_in,
                              void* d_out, int out_size)
{
    const float* tgt       = (const float*)d_in[0];
    const float* query_pos = (const float*)d_in[1];
    const float* refpts    = (const float*)d_in[4];
    const float* src       = (const float*)d_in[6];
    const float* W_dsa = (const float*)d_in[10]; const float* b_dsa = (const float*)d_in[11];
    const float* g_nds = (const float*)d_in[12]; const float* b_nds = (const float*)d_in[13];
    const float* W_off = (const float*)d_in[14]; const float* b_off = (const float*)d_in[15];
    const float* W_att = (const float*)d_in[16]; const float* b_att = (const float*)d_in[17];
    const float* W_val = (const float*)d_in[18]; const float* b_val = (const float*)d_in[19];
    const float* W_out = (const float*)d_in[20]; const float* b_out = (const float*)d_in[21];
    const float* W_csa = (const float*)d_in[22]; const float* b_csa = (const float*)d_in[23];
    const float* g_n1  = (const float*)d_in[24]; const float* b_n1  = (const float*)d_in[25];
    const float* W_ff  = (const float*)d_in[26]; const float* b_ff  = (const float*)d_in[27];
    const float* g_n3  = (const float*)d_in[28]; const float* b_n3  = (const float*)d_in[29];
    float* out = (float*)d_out;

    float *buf0, *buf1, *buf2, *oa, *boa, *bcomb;
    __half *sf16, *wth, *woah;
    cudaGetSymbolAddress((void**)&buf0,  g_buf0);
    cudaGetSymbolAddress((void**)&buf1,  g_buf1);
    cudaGetSymbolAddress((void**)&buf2,  g_buf2);
    cudaGetSymbolAddress((void**)&oa,    g_oa);
    cudaGetSymbolAddress((void**)&boa,   g_boa);
    cudaGetSymbolAddress((void**)&bcomb, g_bcomb);
    cudaGetSymbolAddress((void**)&sf16,  g_sf16);
    cudaGetSymbolAddress((void**)&wth,   g_wt_h16);
    cudaGetSymbolAddress((void**)&woah,  g_woa_h16);

    cudaFuncSetAttribute((const void*)mgemm_kernel<false>,
                         cudaFuncAttributeMaxDynamicSharedMemorySize, GSMEM);
    cudaFuncSetAttribute((const void*)mgemm_kernel<true>,
                         cudaFuncAttributeMaxDynamicSharedMemorySize, GSMEM);

    const int MT  = (ROWS + 127) / 128;       // 235 row tiles
    const dim3 gFull(MT, 2);                  // N = 256
    const dim3 gOA  (MT, 1);                  // N = 128 (96 padded)
    const int EW8 = (ROWS * CDIM / 8 + 255) / 256;
    const int LNB = ROWS / 8;                 // 3750 warp-LN blocks

    // 0) combined weight + prep
    comb_kernel<<<256, 256>>>(W_out, W_csa, b_out, b_csa);
    prep_kernel<<<(PREP_TOT + 255) / 256, 256>>>(W_dsa, W_val, W_ff,
                                                 W_off, W_att, b_off, b_att);
    // 1) src -> fp16
    cvt_f16_kernel<<<EW8, 256>>>(src, sf16);
    // 2) dsa GEMM -> buf0 (f32)
    mgemm_kernel<false><<<gFull, 128, GSMEM>>>(
        sf16, wth + 0 * 65536, b_dsa, buf0, 256);
    // 3) LN(nds) -> fp16
    ln_f16_warp<<<LNB, 256>>>(buf0, g_nds, b_nds, sf16);
    // 4) value GEMM -> buf0 (f32)
    mgemm_kernel<false><<<gFull, 128, GSMEM>>>(
        sf16, wth + 1 * 65536, b_val, buf0, 256);
    // 5) q = tgt + query_pos -> fp16
    add_f16_kernel<<<EW8, 256>>>(tgt, query_pos, sf16);
    // 6) offsets+attention GEMM (N=128 padded) -> oa
    mgemm_kernel<false><<<gOA, 128, GSMEM>>>(
        sf16, woah, boa, oa, 128);
    // 7) deformable sampling -> fp16 (sf16)
    msda_kernel<<<(ROWS * HEADS + 7) / 8, 256>>>(buf0, oa, refpts, sf16);
    // 8) combined out+csa GEMM -> buf1 (f32)
    mgemm_kernel<false><<<gFull, 128, GSMEM>>>(
        sf16, wth + 2 * 65536, bcomb, buf1, 256);
    // 9) t = LN(tgt + tgt2) -> buf2 (f32) + fp16
    addln_f16_warp<<<LNB, 256>>>(tgt, buf1, g_n1, b_n1, buf2, sf16);
    // 10) ff = gelu(t @ W_ff + b_ff) -> buf0 (f32)
    mgemm_kernel<true><<<gFull, 128, GSMEM>>>(
        sf16, wth + 3 * 65536, b_ff, buf0, 256);
    // 11) out = LN(t + ff)
    addln_warp<<<LNB, 256>>>(buf2, buf0, g_n3, b_n3, out);
}